// round 2
// baseline (speedup 1.0000x reference)
#include <cuda_runtime.h>
#include <math.h>

#define SEQ   2048
#define DMODEL 2048
#define NHEAD 32
#define NKV   8
#define HDIM  64
#define NEXP  8
#define FDIM  7168
#define NTOK  2048
#define NSLOT 4096
#define EPSF  1e-5f

// ----------------------------- scratch (device globals; no runtime alloc) ---
__device__ float g_hnorm[NTOK * DMODEL];
__device__ float g_q[NTOK * NHEAD * HDIM];
__device__ float g_k[NTOK * NKV * HDIM];
__device__ float g_v[NTOK * NKV * HDIM];
__device__ float g_attn[NTOK * DMODEL];
__device__ float g_h2[NTOK * DMODEL];
__device__ float g_tnorm[NTOK * DMODEL];
__device__ int   g_topi[NTOK * 2];
__device__ float g_topw[NTOK * 2];
__device__ int   g_slot_token[NSLOT];
__device__ int   g_slot_of[NTOK * 2];
__device__ int   g_off[NEXP + 1];
__device__ float g_act[(size_t)NSLOT * FDIM];    // silu(gate)*up per slot
__device__ float g_down[(size_t)NSLOT * DMODEL]; // expert down output per slot

// ----------------------------- RMSNorm --------------------------------------
__global__ __launch_bounds__(256) void rmsnorm_kernel(
    const float* __restrict__ x, const float* __restrict__ w, float* __restrict__ y)
{
    int row = blockIdx.x;
    const float* xr = x + (size_t)row * DMODEL;
    __shared__ float red[256];
    float ss = 0.f;
    const float4* x4 = (const float4*)xr;
    for (int i = threadIdx.x; i < DMODEL / 4; i += 256) {
        float4 v = x4[i];
        ss += v.x * v.x + v.y * v.y + v.z * v.z + v.w * v.w;
    }
    red[threadIdx.x] = ss;
    __syncthreads();
    for (int s = 128; s > 0; s >>= 1) {
        if (threadIdx.x < s) red[threadIdx.x] += red[threadIdx.x + s];
        __syncthreads();
    }
    float inv = rsqrtf(red[0] / (float)DMODEL + EPSF);
    for (int i = threadIdx.x; i < DMODEL; i += 256)
        y[(size_t)row * DMODEL + i] = xr[i] * inv * w[i];
}

// ----------------------------- generic SGEMM (dims multiples of 64) ---------
// C[M,N] = A[M,K] @ B[K,N]  (+ res), all row-major fp32.
__global__ __launch_bounds__(256) void sgemm_kernel(
    const float* __restrict__ A, const float* __restrict__ B,
    float* __restrict__ C, const float* __restrict__ res,
    int M, int N, int K)
{
    __shared__ float As[16][64];   // transposed: As[k][m]
    __shared__ float Bs[16][64];   // Bs[k][n]
    int tid = threadIdx.x;
    int m0 = blockIdx.y * 64, n0 = blockIdx.x * 64;
    int row = (tid >> 4) * 4, col = (tid & 15) * 4;
    int lm = tid >> 2, lk = (tid & 3) * 4;
    int bk = tid >> 4, bn = (tid & 15) * 4;
    const float* aptr = A + (size_t)(m0 + lm) * K + lk;
    const float* bptr = B + (size_t)bk * N + n0 + bn;
    float acc[4][4] = {};
    for (int k0 = 0; k0 < K; k0 += 16) {
        float4 av = *(const float4*)(aptr + k0);
        As[lk + 0][lm] = av.x; As[lk + 1][lm] = av.y;
        As[lk + 2][lm] = av.z; As[lk + 3][lm] = av.w;
        *(float4*)&Bs[bk][bn] = *(const float4*)(bptr + (size_t)k0 * N);
        __syncthreads();
#pragma unroll
        for (int kk = 0; kk < 16; kk++) {
            float4 a = *(float4*)&As[kk][row];
            float4 b = *(float4*)&Bs[kk][col];
            float ar[4] = {a.x, a.y, a.z, a.w};
            float br[4] = {b.x, b.y, b.z, b.w};
#pragma unroll
            for (int i = 0; i < 4; i++)
#pragma unroll
                for (int j = 0; j < 4; j++) acc[i][j] += ar[i] * br[j];
        }
        __syncthreads();
    }
#pragma unroll
    for (int i = 0; i < 4; i++) {
        size_t off = (size_t)(m0 + row + i) * N + n0 + col;
        float4 c = make_float4(acc[i][0], acc[i][1], acc[i][2], acc[i][3]);
        if (res) {
            float4 r = *(const float4*)(res + off);
            c.x += r.x; c.y += r.y; c.z += r.z; c.w += r.w;
        }
        *(float4*)(C + off) = c;
    }
}

// ----------------------------- RoPE (in place) -------------------------------
__global__ void rope_kernel(float* __restrict__ x, const int* __restrict__ pos, int nheads)
{
    int s = blockIdx.x, h = blockIdx.y, i = threadIdx.x; // 32 threads
    float p = (float)pos[s];
    // inv = ROPE_BASE^{-(2i/HD)} = exp(-(2i/64)*ln(1e6))
    float inv = expf(-((float)(2 * i) / 64.f) * 13.815510557964274f);
    float ang = p * inv;
    float sn, cs;
    sincosf(ang, &sn, &cs);
    float* xp = x + ((size_t)s * nheads + h) * HDIM;
    float x1 = xp[i], x2 = xp[i + 32];
    xp[i]      = x1 * cs - x2 * sn;
    xp[i + 32] = x2 * cs + x1 * sn;
}

// ----------------------------- flash attention (causal, GQA) ----------------
// grid: (SEQ/64, NKV); 256 threads = 64 q-positions x 4 q-heads sharing K/V head.
__global__ __launch_bounds__(256) void flash_kernel(float* __restrict__ out)
{
    int bq = blockIdx.x, kvh = blockIdx.y;
    int tid = threadIdx.x;
    int ql = tid & 63, sub = tid >> 6;
    int qpos = bq * 64 + ql;
    int qh = kvh * 4 + sub;
    __shared__ float Ks[32][64];
    __shared__ float Vs[32][64];
    float qreg[64], o[64];
    const float* qp = g_q + ((size_t)qpos * NHEAD + qh) * HDIM;
#pragma unroll
    for (int d = 0; d < 64; d++) { qreg[d] = qp[d] * 0.125f; o[d] = 0.f; }
    float m = -INFINITY, l = 0.f;
    int kend = bq * 64 + 64;
    for (int kt = 0; kt < kend; kt += 32) {
        for (int i = tid; i < 32 * 16; i += 256) {   // 512 float4 loads per buffer
            int j = i >> 4, d4 = (i & 15) * 4;
            *(float4*)&Ks[j][d4] = *(const float4*)(g_k + ((size_t)(kt + j) * NKV + kvh) * HDIM + d4);
            *(float4*)&Vs[j][d4] = *(const float4*)(g_v + ((size_t)(kt + j) * NKV + kvh) * HDIM + d4);
        }
        __syncthreads();
        int jmax = qpos - kt + 1;
        if (jmax > 32) jmax = 32;
        for (int j = 0; j < jmax; j++) {
            float s = 0.f;
#pragma unroll
            for (int d = 0; d < 64; d++) s += qreg[d] * Ks[j][d];
            float mn = fmaxf(m, s);
            float corr = expf(m - mn);
            float p = expf(s - mn);
            l = l * corr + p;
#pragma unroll
            for (int d = 0; d < 64; d++) o[d] = o[d] * corr + p * Vs[j][d];
            m = mn;
        }
        __syncthreads();
    }
    float invl = 1.f / l;
    float* op = out + ((size_t)qpos * NHEAD + qh) * HDIM;
#pragma unroll
    for (int d = 0; d < 64; d++) op[d] = o[d] * invl;
}

// ----------------------------- router: logits + top-2 + renorm --------------
__global__ __launch_bounds__(128) void router_kernel(
    const float* __restrict__ T, const float* __restrict__ Wr)
{
    int t = blockIdx.x;
    __shared__ float sred[128 * 8];
    float acc[8] = {};
    const float* tr = T + (size_t)t * DMODEL;
    for (int d = threadIdx.x; d < DMODEL; d += 128) {
        float x = tr[d];
        const float* wr = Wr + (size_t)d * NEXP;
#pragma unroll
        for (int e = 0; e < 8; e++) acc[e] += x * wr[e];
    }
#pragma unroll
    for (int e = 0; e < 8; e++) sred[threadIdx.x * 8 + e] = acc[e];
    __syncthreads();
    for (int s = 64; s > 0; s >>= 1) {
        if (threadIdx.x < s) {
#pragma unroll
            for (int e = 0; e < 8; e++)
                sred[threadIdx.x * 8 + e] += sred[(threadIdx.x + s) * 8 + e];
        }
        __syncthreads();
    }
    if (threadIdx.x == 0) {
        float best = -1e30f, second = -1e30f;
        int bi = 0, si = 0;
#pragma unroll
        for (int e = 0; e < 8; e++) {
            float v = sred[e];
            if (v > best)      { second = best; si = bi; best = v; bi = e; }
            else if (v > second) { second = v; si = e; }
        }
        // renormalized top-2 softmax weights: softmax norm cancels
        float p0 = 1.f / (1.f + expf(second - best));
        g_topi[2 * t] = bi;  g_topi[2 * t + 1] = si;
        g_topw[2 * t] = p0;  g_topw[2 * t + 1] = 1.f - p0;
    }
}

// ----------------------------- expert assignment (1 block) ------------------
__global__ __launch_bounds__(256) void assign_kernel()
{
    __shared__ int cnt[NEXP], base[NEXP + 1], cur[NEXP];
    if (threadIdx.x < NEXP) cnt[threadIdx.x] = 0;
    __syncthreads();
    for (int t = threadIdx.x; t < NTOK; t += 256) {
        atomicAdd(&cnt[g_topi[2 * t]], 1);
        atomicAdd(&cnt[g_topi[2 * t + 1]], 1);
    }
    __syncthreads();
    if (threadIdx.x == 0) {
        int s = 0;
        for (int e = 0; e < NEXP; e++) { base[e] = s; s += cnt[e]; }
        base[NEXP] = s;
    }
    __syncthreads();
    if (threadIdx.x < NEXP) cur[threadIdx.x] = base[threadIdx.x];
    if (threadIdx.x < NEXP + 1) g_off[threadIdx.x] = base[threadIdx.x];
    __syncthreads();
    for (int t = threadIdx.x; t < NTOK; t += 256) {
#pragma unroll
        for (int k = 0; k < 2; k++) {
            int e = g_topi[2 * t + k];
            int slot = atomicAdd(&cur[e], 1);
            g_slot_token[slot] = t;
            g_slot_of[2 * t + k] = slot;
        }
    }
}

// ----------------------------- grouped gate+up GEMM with SiLU ---------------
// act[slot, f] = silu(T@W1[e]) * (T@W3[e]) over this expert's gathered tokens.
__global__ __launch_bounds__(256) void moe_gateup_kernel(
    const float* __restrict__ T, const float* __restrict__ W1, const float* __restrict__ W3)
{
    int e = blockIdx.z;
    int rbeg = g_off[e], rend = g_off[e + 1];
    int rows = rend - rbeg;
    int m0 = blockIdx.y * 64;
    if (m0 >= rows) return;
    int n0 = blockIdx.x * 64;
    const float* B1 = W1 + (size_t)e * DMODEL * FDIM;
    const float* B2 = W3 + (size_t)e * DMODEL * FDIM;
    __shared__ float As[16][64];
    __shared__ float B1s[16][64];
    __shared__ float B2s[16][64];
    int tid = threadIdx.x;
    int row = (tid >> 4) * 4, col = (tid & 15) * 4;
    int lm = tid >> 2, lk = (tid & 3) * 4;
    int bk = tid >> 4, bn = (tid & 15) * 4;
    const float* arow = nullptr;
    if (m0 + lm < rows)
        arow = T + (size_t)g_slot_token[rbeg + m0 + lm] * DMODEL + lk;
    const float* b1ptr = B1 + (size_t)bk * FDIM + n0 + bn;
    const float* b2ptr = B2 + (size_t)bk * FDIM + n0 + bn;
    float accg[4][4] = {}, accu[4][4] = {};
    for (int k0 = 0; k0 < DMODEL; k0 += 16) {
        float4 av = arow ? *(const float4*)(arow + k0) : make_float4(0.f, 0.f, 0.f, 0.f);
        As[lk + 0][lm] = av.x; As[lk + 1][lm] = av.y;
        As[lk + 2][lm] = av.z; As[lk + 3][lm] = av.w;
        *(float4*)&B1s[bk][bn] = *(const float4*)(b1ptr + (size_t)k0 * FDIM);
        *(float4*)&B2s[bk][bn] = *(const float4*)(b2ptr + (size_t)k0 * FDIM);
        __syncthreads();
#pragma unroll
        for (int kk = 0; kk < 16; kk++) {
            float4 a  = *(float4*)&As[kk][row];
            float4 b1 = *(float4*)&B1s[kk][col];
            float4 b2 = *(float4*)&B2s[kk][col];
            float ar[4] = {a.x, a.y, a.z, a.w};
            float g1[4] = {b1.x, b1.y, b1.z, b1.w};
            float g2[4] = {b2.x, b2.y, b2.z, b2.w};
#pragma unroll
            for (int i = 0; i < 4; i++)
#pragma unroll
                for (int j = 0; j < 4; j++) {
                    accg[i][j] += ar[i] * g1[j];
                    accu[i][j] += ar[i] * g2[j];
                }
        }
        __syncthreads();
    }
#pragma unroll
    for (int i = 0; i < 4; i++) {
        int mloc = m0 + row + i;
        if (mloc < rows) {
            size_t slot = (size_t)(rbeg + mloc);
#pragma unroll
            for (int j = 0; j < 4; j++) {
                float g = accg[i][j], u = accu[i][j];
                float sg = g / (1.f + expf(-g));
                g_act[slot * FDIM + n0 + col + j] = sg * u;
            }
        }
    }
}

// ----------------------------- grouped down GEMM -----------------------------
__global__ __launch_bounds__(256) void moe_down_kernel(const float* __restrict__ W2)
{
    int e = blockIdx.z;
    int rbeg = g_off[e], rend = g_off[e + 1];
    int rows = rend - rbeg;
    int m0 = blockIdx.y * 64;
    if (m0 >= rows) return;
    int n0 = blockIdx.x * 64;
    const float* B = W2 + (size_t)e * FDIM * DMODEL;
    __shared__ float As[16][64];
    __shared__ float Bs[16][64];
    int tid = threadIdx.x;
    int row = (tid >> 4) * 4, col = (tid & 15) * 4;
    int lm = tid >> 2, lk = (tid & 3) * 4;
    int bk = tid >> 4, bn = (tid & 15) * 4;
    const float* arow = nullptr;
    if (m0 + lm < rows)
        arow = g_act + (size_t)(rbeg + m0 + lm) * FDIM + lk;
    const float* bptr = B + (size_t)bk * DMODEL + n0 + bn;
    float acc[4][4] = {};
    for (int k0 = 0; k0 < FDIM; k0 += 16) {
        float4 av = arow ? *(const float4*)(arow + k0) : make_float4(0.f, 0.f, 0.f, 0.f);
        As[lk + 0][lm] = av.x; As[lk + 1][lm] = av.y;
        As[lk + 2][lm] = av.z; As[lk + 3][lm] = av.w;
        *(float4*)&Bs[bk][bn] = *(const float4*)(bptr + (size_t)k0 * DMODEL);
        __syncthreads();
#pragma unroll
        for (int kk = 0; kk < 16; kk++) {
            float4 a = *(float4*)&As[kk][row];
            float4 b = *(float4*)&Bs[kk][col];
            float ar[4] = {a.x, a.y, a.z, a.w};
            float br[4] = {b.x, b.y, b.z, b.w};
#pragma unroll
            for (int i = 0; i < 4; i++)
#pragma unroll
                for (int j = 0; j < 4; j++) acc[i][j] += ar[i] * br[j];
        }
        __syncthreads();
    }
#pragma unroll
    for (int i = 0; i < 4; i++) {
        int mloc = m0 + row + i;
        if (mloc < rows) {
            size_t slot = (size_t)(rbeg + mloc);
            float4 c = make_float4(acc[i][0], acc[i][1], acc[i][2], acc[i][3]);
            *(float4*)(g_down + slot * DMODEL + n0 + col) = c;
        }
    }
}

// ----------------------------- final combine ---------------------------------
__global__ __launch_bounds__(256) void combine_kernel(
    const float* __restrict__ h2, float* __restrict__ out)
{
    int t = blockIdx.x;
    int s0 = g_slot_of[2 * t], s1 = g_slot_of[2 * t + 1];
    float w0 = g_topw[2 * t], w1 = g_topw[2 * t + 1];
    const float* d0 = g_down + (size_t)s0 * DMODEL;
    const float* d1 = g_down + (size_t)s1 * DMODEL;
    const float* hr = h2 + (size_t)t * DMODEL;
    float* orow = out + (size_t)t * DMODEL;
    for (int d = threadIdx.x; d < DMODEL; d += 256)
        orow[d] = hr[d] + w0 * d0[d] + w1 * d1[d];
}

// ----------------------------- launch ---------------------------------------
extern "C" void kernel_launch(void* const* d_in, const int* in_sizes, int n_in,
                              void* d_out, int out_size)
{
    const float* hs   = (const float*)d_in[0];
    const int*   pos  = (const int*)d_in[1];
    const float* ln1w = (const float*)d_in[2];
    const float* Wq   = (const float*)d_in[3];
    const float* Wk   = (const float*)d_in[4];
    const float* Wv   = (const float*)d_in[5];
    const float* Wo   = (const float*)d_in[6];
    const float* ln2w = (const float*)d_in[7];
    const float* Wr   = (const float*)d_in[8];
    const float* W1   = (const float*)d_in[9];
    const float* W3   = (const float*)d_in[10];
    const float* W2   = (const float*)d_in[11];
    float* out = (float*)d_out;

    float *hnorm, *q, *k, *v, *attn, *h2, *tnorm;
    cudaGetSymbolAddress((void**)&hnorm, g_hnorm);
    cudaGetSymbolAddress((void**)&q, g_q);
    cudaGetSymbolAddress((void**)&k, g_k);
    cudaGetSymbolAddress((void**)&v, g_v);
    cudaGetSymbolAddress((void**)&attn, g_attn);
    cudaGetSymbolAddress((void**)&h2, g_h2);
    cudaGetSymbolAddress((void**)&tnorm, g_tnorm);

    // 1. RMSNorm 1
    rmsnorm_kernel<<<NTOK, 256>>>(hs, ln1w, hnorm);
    // 2. QKV projections
    sgemm_kernel<<<dim3(DMODEL / 64, NTOK / 64), 256>>>(hnorm, Wq, q, nullptr, NTOK, DMODEL, DMODEL);
    sgemm_kernel<<<dim3(512 / 64, NTOK / 64), 256>>>(hnorm, Wk, k, nullptr, NTOK, 512, DMODEL);
    sgemm_kernel<<<dim3(512 / 64, NTOK / 64), 256>>>(hnorm, Wv, v, nullptr, NTOK, 512, DMODEL);
    // 3. RoPE on q and k
    rope_kernel<<<dim3(SEQ, NHEAD), 32>>>(q, pos, NHEAD);
    rope_kernel<<<dim3(SEQ, NKV), 32>>>(k, pos, NKV);
    // 4. causal flash attention
    flash_kernel<<<dim3(SEQ / 64, NKV), 256>>>(attn);
    // 5. O projection + residual
    sgemm_kernel<<<dim3(DMODEL / 64, NTOK / 64), 256>>>(attn, Wo, h2, hs, NTOK, DMODEL, DMODEL);
    // 6. RMSNorm 2
    rmsnorm_kernel<<<NTOK, 256>>>(h2, ln2w, tnorm);
    // 7. router (top-2 + renormalized weights)
    router_kernel<<<NTOK, 128>>>(tnorm, Wr);
    // 8. expert assignment (counts / prefix / slots)
    assign_kernel<<<1, 256>>>();
    // 9. grouped gate+up GEMM with fused SiLU*up
    moe_gateup_kernel<<<dim3(FDIM / 64, NTOK / 64, NEXP), 256>>>(tnorm, W1, W3);
    // 10. grouped down GEMM
    moe_down_kernel<<<dim3(DMODEL / 64, NTOK / 64, NEXP), 256>>>(W2);
    // 11. combine with residual
    combine_kernel<<<NTOK, 256>>>(h2, out);
}

// round 4
// speedup vs baseline: 1.4094x; 1.4094x over previous
#include <cuda_runtime.h>
#include <cuda_bf16.h>
#include <math.h>
#include <stdint.h>

#define SEQ    2048
#define DMODEL 2048
#define NHEAD  32
#define NKV    8
#define HDIM   64
#define NEXP   8
#define FDIM   7168
#define NTOK   2048
#define NSLOT  4096
#define EPSF   1e-5f

typedef __nv_bfloat16 bf16;

// ---------------- device scratch ----------------
__device__ bf16  g_hn_hi[NTOK * DMODEL], g_hn_lo[NTOK * DMODEL];
__device__ float g_q[NTOK * NHEAD * HDIM], g_k[NTOK * NKV * HDIM], g_v[NTOK * NKV * HDIM];
__device__ bf16  g_at_hi[NTOK * DMODEL], g_at_lo[NTOK * DMODEL];
__device__ float g_h2[NTOK * DMODEL], g_tn[NTOK * DMODEL];
__device__ bf16  g_tn_hi[NTOK * DMODEL], g_tn_lo[NTOK * DMODEL];
__device__ int   g_topi[NTOK * 2];
__device__ float g_topw[NTOK * 2];
__device__ int   g_slot_token[NSLOT], g_slot_of[NTOK * 2], g_off[NEXP + 1];
__device__ float g_gate[(size_t)NSLOT * FDIM], g_up[(size_t)NSLOT * FDIM];
__device__ bf16  g_act_hi[(size_t)NSLOT * FDIM], g_act_lo[(size_t)NSLOT * FDIM];
__device__ float g_down[(size_t)NSLOT * DMODEL];

// ---------------- helpers ----------------
__device__ __forceinline__ uint32_t smem_u32(const void* p) {
    uint32_t a;
    asm("{ .reg .u64 t; cvta.to.shared.u64 t, %1; cvt.u32.u64 %0, t; }" : "=r"(a) : "l"(p));
    return a;
}
__device__ __forceinline__ void ldsm4(uint32_t* r, uint32_t addr) {
    asm volatile("ldmatrix.sync.aligned.m8n8.x4.shared.b16 {%0,%1,%2,%3}, [%4];"
                 : "=r"(r[0]), "=r"(r[1]), "=r"(r[2]), "=r"(r[3]) : "r"(addr));
}
__device__ __forceinline__ void mma16816(float* c, const uint32_t* a, const uint32_t* b) {
    asm volatile(
        "mma.sync.aligned.m16n8k16.row.col.f32.bf16.bf16.f32 "
        "{%0,%1,%2,%3}, {%4,%5,%6,%7}, {%8,%9}, {%0,%1,%2,%3};"
        : "+f"(c[0]), "+f"(c[1]), "+f"(c[2]), "+f"(c[3])
        : "r"(a[0]), "r"(a[1]), "r"(a[2]), "r"(a[3]), "r"(b[0]), "r"(b[1]));
}
__device__ __forceinline__ void bfsplit(float x, bf16& h, bf16& l) {
    h = __float2bfloat16_rn(x);
    l = __float2bfloat16_rn(x - __bfloat162float(h));
}

// smem geometry for tc_gemm
#define KC    64            // k-chunk
#define ASTR  72            // A smem row stride (elems) — conflict-free for ldmatrix
#define BSTR  72            // B smem row stride (elems, n-major rows of k)
#define OFF_AH 0
#define OFF_AL (512 * ASTR * 2)                 // 73728
#define OFF_BH (2 * 512 * ASTR * 2)             // 147456
#define OFF_BL (2 * 512 * ASTR * 2 + 64 * BSTR * 2)  // 156672
#define GEMM_SMEM (2 * 512 * ASTR * 2 + 2 * 64 * BSTR * 2)  // 165888

// ======================= HMMA GEMM (3-term bf16 split) =======================
// C[row,N] = A[row,K] @ B[K,N] (+res). A = Ahi+Alo bf16 row-major. B fp32 row-major.
// grouped: expert=blockIdx.z, rows from g_off; gather: A row via g_slot_token.
// Block: 256 thr, tile 512(m, 4 subtiles)x64(n), k-chunk 64.
__global__ __launch_bounds__(256, 1) void tc_gemm(
    const bf16* __restrict__ Ahi, const bf16* __restrict__ Alo,
    const float* __restrict__ B, float* __restrict__ C, const float* __restrict__ res,
    int M, int N, int K, int grouped, int gather)
{
    int e = blockIdx.z;
    int rbeg = 0, rows = M;
    if (grouped) { rbeg = g_off[e]; rows = g_off[e + 1] - rbeg; }
    int mg0 = blockIdx.y * 512;
    if (mg0 >= rows) return;
    int n0 = blockIdx.x * 64;
    const float* Bp = B + (size_t)e * K * N;

    extern __shared__ char sm[];
    bf16* Ah = (bf16*)(sm + OFF_AH);
    bf16* Al = (bf16*)(sm + OFF_AL);
    bf16* Bh = (bf16*)(sm + OFF_BH);
    bf16* Bl = (bf16*)(sm + OFF_BL);
    uint32_t ah_b = smem_u32(Ah), al_b = smem_u32(Al);

    int tid = threadIdx.x, lane = tid & 31, warp = tid >> 5;
    int wm = warp >> 2, wn = warp & 3;   // 2 x 4 warp grid

    float acc[4][4][2][4];
#pragma unroll
    for (int a = 0; a < 4; a++)
#pragma unroll
        for (int b = 0; b < 4; b++)
#pragma unroll
            for (int c = 0; c < 2; c++)
#pragma unroll
                for (int d = 0; d < 4; d++) acc[a][b][c][d] = 0.f;

    int nchunk = K / KC;
    for (int ch = 0; ch < nchunk; ch++) {
        int k0 = ch * KC;
        // ---- load A: 512 rows x 64 (hi+lo), uint4 = 8 bf16 ----
#pragma unroll
        for (int it = 0; it < 16; it++) {
            int idx = tid + it * 256;          // 0..4095
            int row = idx >> 3, seg = idx & 7;
            int m = mg0 + row;
            int rg;
            if (gather)       rg = (m < rows) ? g_slot_token[rbeg + m] : 0;
            else if (grouped) rg = (m < rows) ? (rbeg + m) : rbeg;
            else              rg = (m < rows) ? m : 0;
            const uint4* src_h = (const uint4*)(Ahi + (size_t)rg * K + k0);
            const uint4* src_l = (const uint4*)(Alo + (size_t)rg * K + k0);
            *(uint4*)&Ah[row * ASTR + seg * 8] = src_h[seg];
            *(uint4*)&Al[row * ASTR + seg * 8] = src_l[seg];
        }
        // ---- load B: 64 k x 64 n fp32 -> split, store n-major [n][k] ----
#pragma unroll
        for (int it = 0; it < 4; it++) {
            int idx = tid + it * 256;          // 0..1023
            int kk = idx >> 4, n4 = (idx & 15) * 4;
            float4 v = *(const float4*)(Bp + (size_t)(k0 + kk) * N + n0 + n4);
            float xs[4] = {v.x, v.y, v.z, v.w};
#pragma unroll
            for (int j = 0; j < 4; j++) {
                bf16 h, l;
                bfsplit(xs[j], h, l);
                Bh[(n4 + j) * BSTR + kk] = h;
                Bl[(n4 + j) * BSTR + kk] = l;
            }
        }
        __syncthreads();
        // ---- compute ----
#pragma unroll
        for (int kf = 0; kf < 4; kf++) {
            uint32_t bh[2][2], bl[2][2];
            int kb = kf * 16 + (lane & 3) * 2;
#pragma unroll
            for (int nf = 0; nf < 2; nf++) {
                int n = wn * 16 + nf * 8 + (lane >> 2);
                bh[nf][0] = *(const uint32_t*)&Bh[n * BSTR + kb];
                bh[nf][1] = *(const uint32_t*)&Bh[n * BSTR + kb + 8];
                bl[nf][0] = *(const uint32_t*)&Bl[n * BSTR + kb];
                bl[nf][1] = *(const uint32_t*)&Bl[n * BSTR + kb + 8];
            }
#pragma unroll
            for (int mt = 0; mt < 4; mt++) {
#pragma unroll
                for (int mf = 0; mf < 4; mf++) {
                    int r = mt * 128 + wm * 64 + mf * 16 + (lane & 15);
                    uint32_t boff = (uint32_t)(r * ASTR + kf * 16 + (lane >> 4) * 8) * 2u;
                    uint32_t ah[4], al[4];
                    ldsm4(ah, ah_b + boff);
                    ldsm4(al, al_b + boff);
#pragma unroll
                    for (int nf = 0; nf < 2; nf++) {
                        mma16816(acc[mt][mf][nf], ah, bh[nf]);
                        mma16816(acc[mt][mf][nf], ah, bl[nf]);
                        mma16816(acc[mt][mf][nf], al, bh[nf]);
                    }
                }
            }
        }
        __syncthreads();
    }
    // ---- writeback ----
#pragma unroll
    for (int mt = 0; mt < 4; mt++)
#pragma unroll
        for (int mf = 0; mf < 4; mf++) {
            int mlb = mt * 128 + wm * 64 + mf * 16 + (lane >> 2);
#pragma unroll
            for (int half = 0; half < 2; half++) {
                int m = mg0 + mlb + half * 8;
                if (m < rows) {
                    size_t crow = (size_t)(rbeg + m);
                    float* cp = C + crow * N + n0 + wn * 16 + (lane & 3) * 2;
                    const float* rp = res ? res + (size_t)m * N + n0 + wn * 16 + (lane & 3) * 2 : nullptr;
#pragma unroll
                    for (int nf = 0; nf < 2; nf++) {
                        float2 v;
                        v.x = acc[mt][mf][nf][half * 2];
                        v.y = acc[mt][mf][nf][half * 2 + 1];
                        if (rp) { v.x += rp[nf * 8]; v.y += rp[nf * 8 + 1]; }
                        *(float2*)(cp + nf * 8) = v;
                    }
                }
            }
        }
}

// ======================= small kernels =======================
__global__ __launch_bounds__(256) void rmsnorm_kernel(
    const float* __restrict__ x, const float* __restrict__ w,
    float* __restrict__ yf, bf16* __restrict__ yh, bf16* __restrict__ yl)
{
    int row = blockIdx.x;
    const float* xr = x + (size_t)row * DMODEL;
    __shared__ float red[256];
    float ss = 0.f;
    const float4* x4 = (const float4*)xr;
    for (int i = threadIdx.x; i < DMODEL / 4; i += 256) {
        float4 v = x4[i];
        ss += v.x * v.x + v.y * v.y + v.z * v.z + v.w * v.w;
    }
    red[threadIdx.x] = ss;
    __syncthreads();
    for (int s = 128; s > 0; s >>= 1) {
        if (threadIdx.x < s) red[threadIdx.x] += red[threadIdx.x + s];
        __syncthreads();
    }
    float inv = rsqrtf(red[0] / (float)DMODEL + EPSF);
    for (int i = threadIdx.x; i < DMODEL; i += 256) {
        float val = xr[i] * inv * w[i];
        if (yf) yf[(size_t)row * DMODEL + i] = val;
        bf16 h, l;
        bfsplit(val, h, l);
        yh[(size_t)row * DMODEL + i] = h;
        yl[(size_t)row * DMODEL + i] = l;
    }
}

__global__ void rope_kernel(float* __restrict__ x, const int* __restrict__ pos, int nheads)
{
    int s = blockIdx.x, h = blockIdx.y, i = threadIdx.x;
    float p = (float)pos[s];
    float inv = expf(-((float)(2 * i) / 64.f) * 13.815510557964274f);
    float ang = p * inv;
    float sn, cs;
    sincosf(ang, &sn, &cs);
    float* xp = x + ((size_t)s * nheads + h) * HDIM;
    float x1 = xp[i], x2 = xp[i + 32];
    xp[i]      = x1 * cs - x2 * sn;
    xp[i + 32] = x2 * cs + x1 * sn;
}

__global__ __launch_bounds__(256) void flash_kernel()
{
    int bq = blockIdx.x, kvh = blockIdx.y;
    int tid = threadIdx.x;
    int ql = tid & 63, sub = tid >> 6;
    int qpos = bq * 64 + ql;
    int qh = kvh * 4 + sub;
    __shared__ __align__(16) float Ks[32][64];
    __shared__ __align__(16) float Vs[32][64];
    float qreg[64], o[64];
    const float4* qp = (const float4*)(g_q + ((size_t)qpos * NHEAD + qh) * HDIM);
#pragma unroll
    for (int d4 = 0; d4 < 16; d4++) {
        float4 v = qp[d4];
        qreg[4 * d4] = v.x * 0.125f; qreg[4 * d4 + 1] = v.y * 0.125f;
        qreg[4 * d4 + 2] = v.z * 0.125f; qreg[4 * d4 + 3] = v.w * 0.125f;
        o[4 * d4] = 0.f; o[4 * d4 + 1] = 0.f; o[4 * d4 + 2] = 0.f; o[4 * d4 + 3] = 0.f;
    }
    float m = -INFINITY, l = 0.f;
    int kend = bq * 64 + 64;
    for (int kt = 0; kt < kend; kt += 32) {
        for (int i = tid; i < 32 * 16; i += 256) {
            int j = i >> 4, d4 = (i & 15) * 4;
            *(float4*)&Ks[j][d4] = *(const float4*)(g_k + ((size_t)(kt + j) * NKV + kvh) * HDIM + d4);
            *(float4*)&Vs[j][d4] = *(const float4*)(g_v + ((size_t)(kt + j) * NKV + kvh) * HDIM + d4);
        }
        __syncthreads();
        int jmax = qpos - kt + 1;
        if (jmax > 32) jmax = 32;
        int j = 0;
        for (; j + 4 <= jmax; j += 4) {
            float s0 = 0.f, s1 = 0.f, s2 = 0.f, s3 = 0.f;
#pragma unroll
            for (int d = 0; d < 64; d += 4) {
                float4 k0 = *(const float4*)&Ks[j][d];
                float4 k1 = *(const float4*)&Ks[j + 1][d];
                float4 k2 = *(const float4*)&Ks[j + 2][d];
                float4 k3 = *(const float4*)&Ks[j + 3][d];
                s0 += qreg[d] * k0.x + qreg[d + 1] * k0.y + qreg[d + 2] * k0.z + qreg[d + 3] * k0.w;
                s1 += qreg[d] * k1.x + qreg[d + 1] * k1.y + qreg[d + 2] * k1.z + qreg[d + 3] * k1.w;
                s2 += qreg[d] * k2.x + qreg[d + 1] * k2.y + qreg[d + 2] * k2.z + qreg[d + 3] * k2.w;
                s3 += qreg[d] * k3.x + qreg[d + 1] * k3.y + qreg[d + 2] * k3.z + qreg[d + 3] * k3.w;
            }
            float mn = fmaxf(fmaxf(fmaxf(s0, s1), fmaxf(s2, s3)), m);
            float corr = __expf(m - mn);
            float p0 = __expf(s0 - mn), p1 = __expf(s1 - mn);
            float p2 = __expf(s2 - mn), p3 = __expf(s3 - mn);
            l = l * corr + p0 + p1 + p2 + p3;
            m = mn;
#pragma unroll
            for (int d = 0; d < 64; d += 4) {
                float4 v0 = *(const float4*)&Vs[j][d];
                float4 v1 = *(const float4*)&Vs[j + 1][d];
                float4 v2 = *(const float4*)&Vs[j + 2][d];
                float4 v3 = *(const float4*)&Vs[j + 3][d];
                o[d]     = o[d]     * corr + p0 * v0.x + p1 * v1.x + p2 * v2.x + p3 * v3.x;
                o[d + 1] = o[d + 1] * corr + p0 * v0.y + p1 * v1.y + p2 * v2.y + p3 * v3.y;
                o[d + 2] = o[d + 2] * corr + p0 * v0.z + p1 * v1.z + p2 * v2.z + p3 * v3.z;
                o[d + 3] = o[d + 3] * corr + p0 * v0.w + p1 * v1.w + p2 * v2.w + p3 * v3.w;
            }
        }
        for (; j < jmax; j++) {
            float s = 0.f;
#pragma unroll
            for (int d = 0; d < 64; d++) s += qreg[d] * Ks[j][d];
            float mn = fmaxf(m, s);
            float corr = __expf(m - mn);
            float p = __expf(s - mn);
            l = l * corr + p;
#pragma unroll
            for (int d = 0; d < 64; d++) o[d] = o[d] * corr + p * Vs[j][d];
            m = mn;
        }
        __syncthreads();
    }
    float invl = 1.f / l;
    size_t base = (size_t)qpos * DMODEL + (size_t)qh * HDIM;
#pragma unroll
    for (int d = 0; d < 64; d++) {
        float val = o[d] * invl;
        bf16 h, lo;
        bfsplit(val, h, lo);
        g_at_hi[base + d] = h;
        g_at_lo[base + d] = lo;
    }
}

__global__ __launch_bounds__(128) void router_kernel(
    const float* __restrict__ T, const float* __restrict__ Wr)
{
    int t = blockIdx.x;
    __shared__ float sred[128 * 8];
    float acc[8] = {};
    const float* tr = T + (size_t)t * DMODEL;
    for (int d = threadIdx.x; d < DMODEL; d += 128) {
        float x = tr[d];
        const float* wr = Wr + (size_t)d * NEXP;
#pragma unroll
        for (int e = 0; e < 8; e++) acc[e] += x * wr[e];
    }
#pragma unroll
    for (int e = 0; e < 8; e++) sred[threadIdx.x * 8 + e] = acc[e];
    __syncthreads();
    for (int s = 64; s > 0; s >>= 1) {
        if (threadIdx.x < s) {
#pragma unroll
            for (int e = 0; e < 8; e++)
                sred[threadIdx.x * 8 + e] += sred[(threadIdx.x + s) * 8 + e];
        }
        __syncthreads();
    }
    if (threadIdx.x == 0) {
        float best = -1e30f, second = -1e30f;
        int bi = 0, si = 0;
#pragma unroll
        for (int e = 0; e < 8; e++) {
            float v = sred[e];
            if (v > best)        { second = best; si = bi; best = v; bi = e; }
            else if (v > second) { second = v; si = e; }
        }
        float p0 = 1.f / (1.f + expf(second - best));
        g_topi[2 * t] = bi;  g_topi[2 * t + 1] = si;
        g_topw[2 * t] = p0;  g_topw[2 * t + 1] = 1.f - p0;
    }
}

__global__ __launch_bounds__(256) void assign_kernel()
{
    __shared__ int cnt[NEXP], base[NEXP + 1], cur[NEXP];
    if (threadIdx.x < NEXP) cnt[threadIdx.x] = 0;
    __syncthreads();
    for (int t = threadIdx.x; t < NTOK; t += 256) {
        atomicAdd(&cnt[g_topi[2 * t]], 1);
        atomicAdd(&cnt[g_topi[2 * t + 1]], 1);
    }
    __syncthreads();
    if (threadIdx.x == 0) {
        int s = 0;
        for (int e = 0; e < NEXP; e++) { base[e] = s; s += cnt[e]; }
        base[NEXP] = s;
    }
    __syncthreads();
    if (threadIdx.x < NEXP) cur[threadIdx.x] = base[threadIdx.x];
    if (threadIdx.x < NEXP + 1) g_off[threadIdx.x] = base[threadIdx.x];
    __syncthreads();
    for (int t = threadIdx.x; t < NTOK; t += 256) {
#pragma unroll
        for (int k = 0; k < 2; k++) {
            int e = g_topi[2 * t + k];
            int slot = atomicAdd(&cur[e], 1);
            g_slot_token[slot] = t;
            g_slot_of[2 * t + k] = slot;
        }
    }
}

__global__ __launch_bounds__(512) void silu_kernel()
{
    size_t i = ((size_t)blockIdx.x * 512 + threadIdx.x) * 4;
    float4 g = *(const float4*)(g_gate + i);
    float4 u = *(const float4*)(g_up + i);
    float a0 = g.x / (1.f + __expf(-g.x)) * u.x;
    float a1 = g.y / (1.f + __expf(-g.y)) * u.y;
    float a2 = g.z / (1.f + __expf(-g.z)) * u.z;
    float a3 = g.w / (1.f + __expf(-g.w)) * u.w;
    bf16 h0, l0, h1, l1, h2, l2, h3, l3;
    bfsplit(a0, h0, l0); bfsplit(a1, h1, l1);
    bfsplit(a2, h2, l2); bfsplit(a3, h3, l3);
    bf16* ph = g_act_hi + i;
    bf16* pl = g_act_lo + i;
    ph[0] = h0; ph[1] = h1; ph[2] = h2; ph[3] = h3;
    pl[0] = l0; pl[1] = l1; pl[2] = l2; pl[3] = l3;
}

__global__ __launch_bounds__(256) void combine_kernel(
    const float* __restrict__ h2, float* __restrict__ out)
{
    int t = blockIdx.x;
    int s0 = g_slot_of[2 * t], s1 = g_slot_of[2 * t + 1];
    float w0 = g_topw[2 * t], w1 = g_topw[2 * t + 1];
    const float* d0 = g_down + (size_t)s0 * DMODEL;
    const float* d1 = g_down + (size_t)s1 * DMODEL;
    const float* hr = h2 + (size_t)t * DMODEL;
    float* orow = out + (size_t)t * DMODEL;
    for (int d = threadIdx.x; d < DMODEL; d += 256)
        orow[d] = hr[d] + w0 * d0[d] + w1 * d1[d];
}

// ======================= launch =======================
extern "C" void kernel_launch(void* const* d_in, const int* in_sizes, int n_in,
                              void* d_out, int out_size)
{
    const float* hs   = (const float*)d_in[0];
    const int*   pos  = (const int*)d_in[1];
    const float* ln1w = (const float*)d_in[2];
    const float* Wq   = (const float*)d_in[3];
    const float* Wk   = (const float*)d_in[4];
    const float* Wv   = (const float*)d_in[5];
    const float* Wo   = (const float*)d_in[6];
    const float* ln2w = (const float*)d_in[7];
    const float* Wr   = (const float*)d_in[8];
    const float* W1   = (const float*)d_in[9];
    const float* W3   = (const float*)d_in[10];
    const float* W2   = (const float*)d_in[11];
    float* out = (float*)d_out;

    cudaFuncSetAttribute(tc_gemm, cudaFuncAttributeMaxDynamicSharedMemorySize, GEMM_SMEM);

    void* p;
    cudaGetSymbolAddress(&p, g_hn_hi);  bf16* hn_hi = (bf16*)p;
    cudaGetSymbolAddress(&p, g_hn_lo);  bf16* hn_lo = (bf16*)p;
    cudaGetSymbolAddress(&p, g_q);      float* q    = (float*)p;
    cudaGetSymbolAddress(&p, g_k);      float* k    = (float*)p;
    cudaGetSymbolAddress(&p, g_v);      float* v    = (float*)p;
    cudaGetSymbolAddress(&p, g_at_hi);  bf16* at_hi = (bf16*)p;
    cudaGetSymbolAddress(&p, g_at_lo);  bf16* at_lo = (bf16*)p;
    cudaGetSymbolAddress(&p, g_h2);     float* h2   = (float*)p;
    cudaGetSymbolAddress(&p, g_tn);     float* tn   = (float*)p;
    cudaGetSymbolAddress(&p, g_tn_hi);  bf16* tn_hi = (bf16*)p;
    cudaGetSymbolAddress(&p, g_tn_lo);  bf16* tn_lo = (bf16*)p;
    cudaGetSymbolAddress(&p, g_gate);   float* gate = (float*)p;
    cudaGetSymbolAddress(&p, g_up);     float* up   = (float*)p;
    cudaGetSymbolAddress(&p, g_act_hi); bf16* ac_hi = (bf16*)p;
    cudaGetSymbolAddress(&p, g_act_lo); bf16* ac_lo = (bf16*)p;
    cudaGetSymbolAddress(&p, g_down);   float* down = (float*)p;

    // 1. rmsnorm1 -> bf16 hi/lo
    rmsnorm_kernel<<<NTOK, 256>>>(hs, ln1w, nullptr, hn_hi, hn_lo);
    // 2. QKV projections (HMMA)
    tc_gemm<<<dim3(32, 4, 1), 256, GEMM_SMEM>>>(hn_hi, hn_lo, Wq, q, nullptr, NTOK, 2048, DMODEL, 0, 0);
    tc_gemm<<<dim3(8, 4, 1), 256, GEMM_SMEM>>>(hn_hi, hn_lo, Wk, k, nullptr, NTOK, 512, DMODEL, 0, 0);
    tc_gemm<<<dim3(8, 4, 1), 256, GEMM_SMEM>>>(hn_hi, hn_lo, Wv, v, nullptr, NTOK, 512, DMODEL, 0, 0);
    // 3. RoPE
    rope_kernel<<<dim3(SEQ, NHEAD), 32>>>(q, pos, NHEAD);
    rope_kernel<<<dim3(SEQ, NKV), 32>>>(k, pos, NKV);
    // 4. flash attention -> attn hi/lo
    flash_kernel<<<dim3(SEQ / 64, NKV), 256>>>();
    // 5. O projection + residual
    tc_gemm<<<dim3(32, 4, 1), 256, GEMM_SMEM>>>(at_hi, at_lo, Wo, h2, hs, NTOK, 2048, DMODEL, 0, 0);
    // 6. rmsnorm2 -> fp32 (router) + hi/lo (GEMM)
    rmsnorm_kernel<<<NTOK, 256>>>(h2, ln2w, tn, tn_hi, tn_lo);
    // 7-8. router + assignment
    router_kernel<<<NTOK, 128>>>(tn, Wr);
    assign_kernel<<<1, 256>>>();
    // 9. gate & up grouped GEMMs (gather)
    tc_gemm<<<dim3(112, 4, 8), 256, GEMM_SMEM>>>(tn_hi, tn_lo, W1, gate, nullptr, 0, FDIM, DMODEL, 1, 1);
    tc_gemm<<<dim3(112, 4, 8), 256, GEMM_SMEM>>>(tn_hi, tn_lo, W3, up, nullptr, 0, FDIM, DMODEL, 1, 1);
    // 10. silu(gate)*up -> act hi/lo
    silu_kernel<<<(int)((size_t)NSLOT * FDIM / 4 / 512), 512>>>();
    // 11. down grouped GEMM (slot-space A, no gather)
    tc_gemm<<<dim3(32, 4, 8), 256, GEMM_SMEM>>>(ac_hi, ac_lo, W2, down, nullptr, 0, DMODEL, FDIM, 1, 0);
    // 12. combine with residual
    combine_kernel<<<NTOK, 256>>>(h2, out);
}

// round 5
// speedup vs baseline: 1.7527x; 1.2436x over previous
#include <cuda_runtime.h>
#include <cuda_bf16.h>
#include <math.h>
#include <stdint.h>

#define SEQ    2048
#define DMODEL 2048
#define NHEAD  32
#define NKV    8
#define HDIM   64
#define NEXP   8
#define FDIM   7168
#define NTOK   2048
#define NSLOT  4096
#define EPSF   1e-5f

typedef __nv_bfloat16 bf16;

// ---------------- device scratch ----------------
__device__ bf16  g_hn_hi[NTOK * DMODEL], g_hn_lo[NTOK * DMODEL];
__device__ float g_q[NTOK * NHEAD * HDIM], g_k[NTOK * NKV * HDIM], g_v[NTOK * NKV * HDIM];
__device__ bf16  g_at_hi[NTOK * DMODEL], g_at_lo[NTOK * DMODEL];
__device__ float g_h2[NTOK * DMODEL], g_tn[NTOK * DMODEL];
__device__ bf16  g_tn_hi[NTOK * DMODEL], g_tn_lo[NTOK * DMODEL];
__device__ int   g_topi[NTOK * 2];
__device__ float g_topw[NTOK * 2];
__device__ int   g_slot_token[NSLOT], g_slot_of[NTOK * 2], g_off[NEXP + 1];
__device__ float g_gate[(size_t)NSLOT * FDIM], g_up[(size_t)NSLOT * FDIM];
__device__ bf16  g_act_hi[(size_t)NSLOT * FDIM], g_act_lo[(size_t)NSLOT * FDIM];
__device__ float g_down[(size_t)NSLOT * DMODEL];

// ---------------- helpers ----------------
__device__ __forceinline__ uint32_t smem_u32(const void* p) {
    uint32_t a;
    asm("{ .reg .u64 t; cvta.to.shared.u64 t, %1; cvt.u32.u64 %0, t; }" : "=r"(a) : "l"(p));
    return a;
}
__device__ __forceinline__ void ldsm4(uint32_t* r, uint32_t addr) {
    asm volatile("ldmatrix.sync.aligned.m8n8.x4.shared.b16 {%0,%1,%2,%3}, [%4];"
                 : "=r"(r[0]), "=r"(r[1]), "=r"(r[2]), "=r"(r[3]) : "r"(addr));
}
__device__ __forceinline__ void mma16816(float* c, const uint32_t* a, const uint32_t* b) {
    asm volatile(
        "mma.sync.aligned.m16n8k16.row.col.f32.bf16.bf16.f32 "
        "{%0,%1,%2,%3}, {%4,%5,%6,%7}, {%8,%9}, {%0,%1,%2,%3};"
        : "+f"(c[0]), "+f"(c[1]), "+f"(c[2]), "+f"(c[3])
        : "r"(a[0]), "r"(a[1]), "r"(a[2]), "r"(a[3]), "r"(b[0]), "r"(b[1]));
}
__device__ __forceinline__ void cp16(uint32_t dst, const void* src) {
    asm volatile("cp.async.cg.shared.global [%0], [%1], 16;" :: "r"(dst), "l"(src));
}
__device__ __forceinline__ void cp_commit() { asm volatile("cp.async.commit_group;"); }
__device__ __forceinline__ void cp_wait0()  { asm volatile("cp.async.wait_group 0;"); }
__device__ __forceinline__ void bfsplit(float x, bf16& h, bf16& l) {
    h = __float2bfloat16_rn(x);
    l = __float2bfloat16_rn(x - __bfloat162float(h));
}

// ---------------- tc_gemm geometry ----------------
#define BM 256
#define BN 64
#define KC 64
#define ASTR 72
#define BSTR 72
#define OFF_AH(b) (1024u + (b) * 36864u)
#define OFF_AL(b) (1024u + 73728u + (b) * 36864u)
#define OFF_BH(b) (1024u + 147456u + (b) * 9216u)
#define OFF_BL(b) (1024u + 165888u + (b) * 9216u)
#define GEMM_SMEM 185344

__device__ __forceinline__ void gemm_issueA(uint32_t sb, int buf,
    const bf16* __restrict__ Ahi, const bf16* __restrict__ Alo,
    const int* rowg, int K, int k0, int tid)
{
#pragma unroll
    for (int it = 0; it < 4; it++) {
        int idx = tid + it * 512;
        int row = idx >> 3, seg = idx & 7;
        size_t goff = (size_t)rowg[row] * K + k0 + seg * 8;
        uint32_t soff = ((uint32_t)row * ASTR + (uint32_t)seg * 8) * 2u;
        cp16(sb + OFF_AH(buf) + soff, Ahi + goff);
        cp16(sb + OFF_AL(buf) + soff, Alo + goff);
    }
}
__device__ __forceinline__ void gemm_ldgB(const float* __restrict__ Bp, int N, int k0,
                                          int n0, int bn, int bk, float* bst)
{
    const float* p = Bp + (size_t)(k0 + bk) * N + n0 + bn;
#pragma unroll
    for (int j = 0; j < 8; j++) bst[j] = p[(size_t)j * N];
}
__device__ __forceinline__ void gemm_stsB(char* sm, int buf, int bn, int bk, const float* bst)
{
    uint32_t h[4], l[4];
#pragma unroll
    for (int j = 0; j < 4; j++) {
        bf16 h0, l0, h1, l1;
        bfsplit(bst[2 * j], h0, l0);
        bfsplit(bst[2 * j + 1], h1, l1);
        h[j] = (uint32_t)*(unsigned short*)&h0 | ((uint32_t)*(unsigned short*)&h1 << 16);
        l[j] = (uint32_t)*(unsigned short*)&l0 | ((uint32_t)*(unsigned short*)&l1 << 16);
    }
    uint32_t off = ((uint32_t)bn * BSTR + (uint32_t)bk) * 2u;
    *(uint4*)(sm + OFF_BH(buf) + off) = make_uint4(h[0], h[1], h[2], h[3]);
    *(uint4*)(sm + OFF_BL(buf) + off) = make_uint4(l[0], l[1], l[2], l[3]);
}
__device__ __forceinline__ void gemm_compute(uint32_t sb, char* sm, int buf,
                                             int wm, int wn, int lane, float acc[4][2][4])
{
    bf16* Bh = (bf16*)(sm + OFF_BH(buf));
    bf16* Bl = (bf16*)(sm + OFF_BL(buf));
    uint32_t ah_s = sb + OFF_AH(buf), al_s = sb + OFF_AL(buf);
#pragma unroll
    for (int kf = 0; kf < 4; kf++) {
        uint32_t bh[2][2], bl[2][2];
        int kb = kf * 16 + (lane & 3) * 2;
#pragma unroll
        for (int nf = 0; nf < 2; nf++) {
            int n = wn * 16 + nf * 8 + (lane >> 2);
            bh[nf][0] = *(const uint32_t*)&Bh[n * BSTR + kb];
            bh[nf][1] = *(const uint32_t*)&Bh[n * BSTR + kb + 8];
            bl[nf][0] = *(const uint32_t*)&Bl[n * BSTR + kb];
            bl[nf][1] = *(const uint32_t*)&Bl[n * BSTR + kb + 8];
        }
#pragma unroll
        for (int mf = 0; mf < 4; mf++) {
            int r = wm * 64 + mf * 16 + (lane & 15);
            uint32_t boff = ((uint32_t)r * ASTR + (uint32_t)(kf * 16 + (lane >> 4) * 8)) * 2u;
            uint32_t ah[4], al[4];
            ldsm4(ah, ah_s + boff);
            ldsm4(al, al_s + boff);
#pragma unroll
            for (int nf = 0; nf < 2; nf++) {
                mma16816(acc[mf][nf], ah, bh[nf]);
                mma16816(acc[mf][nf], ah, bl[nf]);
                mma16816(acc[mf][nf], al, bh[nf]);
            }
        }
    }
}

// ======================= HMMA GEMM, cp.async double-buffered =======================
// C[row,N] = A[row,K] @ B[K,N] (+res). A = Ahi+Alo bf16 row-major (3-term split).
__global__ __launch_bounds__(512, 1) void tc_gemm(
    const bf16* __restrict__ Ahi, const bf16* __restrict__ Alo,
    const float* __restrict__ B, float* __restrict__ C, const float* __restrict__ res,
    int M, int N, int K, int grouped, int gather)
{
    int e = blockIdx.z;
    int rbeg = 0, rows = M;
    if (grouped) { rbeg = g_off[e]; rows = g_off[e + 1] - rbeg; }
    int mg0 = blockIdx.y * BM;
    if (mg0 >= rows) return;
    int n0 = blockIdx.x * BN;
    const float* Bp = B + (size_t)e * K * N;

    extern __shared__ char sm[];
    uint32_t sb = smem_u32(sm);
    int* rowg = (int*)sm;
    int tid = threadIdx.x, lane = tid & 31, warp = tid >> 5;
    int wm = warp >> 2, wn = warp & 3;

    for (int r = tid; r < BM; r += 512) {
        int m = mg0 + r, rg;
        if (gather)       rg = (m < rows) ? g_slot_token[rbeg + m] : 0;
        else if (grouped) rg = (m < rows) ? (rbeg + m) : rbeg;
        else              rg = (m < rows) ? m : 0;
        rowg[r] = rg;
    }
    __syncthreads();

    float acc[4][2][4];
#pragma unroll
    for (int a = 0; a < 4; a++)
#pragma unroll
        for (int b = 0; b < 2; b++)
#pragma unroll
            for (int c = 0; c < 4; c++) acc[a][b][c] = 0.f;

    int bn = tid & 63, bk = (tid >> 6) * 8;
    float bst[8];
    int NC = K / KC;

    // prologue: chunk 0
    gemm_issueA(sb, 0, Ahi, Alo, rowg, K, 0, tid);
    cp_commit();
    gemm_ldgB(Bp, N, 0, n0, bn, bk, bst);
    cp_wait0();
    __syncthreads();
    gemm_stsB(sm, 0, bn, bk, bst);
    __syncthreads();

    for (int ch = 0; ch < NC; ch++) {
        int buf = ch & 1;
        if (ch + 1 < NC) {
            gemm_issueA(sb, buf ^ 1, Ahi, Alo, rowg, K, (ch + 1) * KC, tid);
            cp_commit();
            gemm_ldgB(Bp, N, (ch + 1) * KC, n0, bn, bk, bst);
        }
        gemm_compute(sb, sm, buf, wm, wn, lane, acc);
        if (ch + 1 < NC) {
            cp_wait0();
            __syncthreads();
            gemm_stsB(sm, buf ^ 1, bn, bk, bst);
            __syncthreads();
        }
    }

    // writeback
#pragma unroll
    for (int mf = 0; mf < 4; mf++) {
#pragma unroll
        for (int half = 0; half < 2; half++) {
            int m = mg0 + wm * 64 + mf * 16 + (lane >> 2) + half * 8;
            if (m < rows) {
                size_t crow = (size_t)(rbeg + m);
                float* cp = C + crow * N + n0 + wn * 16 + (lane & 3) * 2;
                const float* rp = res ? res + (size_t)m * N + n0 + wn * 16 + (lane & 3) * 2 : nullptr;
#pragma unroll
                for (int nf = 0; nf < 2; nf++) {
                    float2 v;
                    v.x = acc[mf][nf][half * 2];
                    v.y = acc[mf][nf][half * 2 + 1];
                    if (rp) { v.x += rp[nf * 8]; v.y += rp[nf * 8 + 1]; }
                    *(float2*)(cp + nf * 8) = v;
                }
            }
        }
    }
}

// ======================= small kernels =======================
__global__ __launch_bounds__(256) void rmsnorm_kernel(
    const float* __restrict__ x, const float* __restrict__ w,
    float* __restrict__ yf, bf16* __restrict__ yh, bf16* __restrict__ yl)
{
    int row = blockIdx.x;
    const float* xr = x + (size_t)row * DMODEL;
    __shared__ float red[256];
    float ss = 0.f;
    const float4* x4 = (const float4*)xr;
    for (int i = threadIdx.x; i < DMODEL / 4; i += 256) {
        float4 v = x4[i];
        ss += v.x * v.x + v.y * v.y + v.z * v.z + v.w * v.w;
    }
    red[threadIdx.x] = ss;
    __syncthreads();
    for (int s = 128; s > 0; s >>= 1) {
        if (threadIdx.x < s) red[threadIdx.x] += red[threadIdx.x + s];
        __syncthreads();
    }
    float inv = rsqrtf(red[0] / (float)DMODEL + EPSF);
    for (int i = threadIdx.x; i < DMODEL; i += 256) {
        float val = xr[i] * inv * w[i];
        if (yf) yf[(size_t)row * DMODEL + i] = val;
        bf16 h, l;
        bfsplit(val, h, l);
        yh[(size_t)row * DMODEL + i] = h;
        yl[(size_t)row * DMODEL + i] = l;
    }
}

__global__ void rope_kernel(float* __restrict__ x, const int* __restrict__ pos, int nheads)
{
    int s = blockIdx.x, h = blockIdx.y, i = threadIdx.x;
    float p = (float)pos[s];
    float inv = expf(-((float)(2 * i) / 64.f) * 13.815510557964274f);
    float ang = p * inv;
    float sn, cs;
    sincosf(ang, &sn, &cs);
    float* xp = x + ((size_t)s * nheads + h) * HDIM;
    float x1 = xp[i], x2 = xp[i + 32];
    xp[i]      = x1 * cs - x2 * sn;
    xp[i + 32] = x2 * cs + x1 * sn;
}

__global__ __launch_bounds__(256) void flash_kernel()
{
    int bq = blockIdx.x, kvh = blockIdx.y;
    int tid = threadIdx.x;
    int ql = tid & 63, sub = tid >> 6;
    int qpos = bq * 64 + ql;
    int qh = kvh * 4 + sub;
    __shared__ __align__(16) float Ks[32][64];
    __shared__ __align__(16) float Vs[32][64];
    float qreg[64], o[64];
    const float4* qp = (const float4*)(g_q + ((size_t)qpos * NHEAD + qh) * HDIM);
#pragma unroll
    for (int d4 = 0; d4 < 16; d4++) {
        float4 v = qp[d4];
        qreg[4 * d4] = v.x * 0.125f; qreg[4 * d4 + 1] = v.y * 0.125f;
        qreg[4 * d4 + 2] = v.z * 0.125f; qreg[4 * d4 + 3] = v.w * 0.125f;
        o[4 * d4] = 0.f; o[4 * d4 + 1] = 0.f; o[4 * d4 + 2] = 0.f; o[4 * d4 + 3] = 0.f;
    }
    float m = -INFINITY, l = 0.f;
    int kend = bq * 64 + 64;
    for (int kt = 0; kt < kend; kt += 32) {
        for (int i = tid; i < 32 * 16; i += 256) {
            int j = i >> 4, d4 = (i & 15) * 4;
            *(float4*)&Ks[j][d4] = *(const float4*)(g_k + ((size_t)(kt + j) * NKV + kvh) * HDIM + d4);
            *(float4*)&Vs[j][d4] = *(const float4*)(g_v + ((size_t)(kt + j) * NKV + kvh) * HDIM + d4);
        }
        __syncthreads();
        int jmax = qpos - kt + 1;
        if (jmax > 32) jmax = 32;
        int j = 0;
        for (; j + 4 <= jmax; j += 4) {
            float s0 = 0.f, s1 = 0.f, s2 = 0.f, s3 = 0.f;
#pragma unroll
            for (int d = 0; d < 64; d += 4) {
                float4 k0 = *(const float4*)&Ks[j][d];
                float4 k1 = *(const float4*)&Ks[j + 1][d];
                float4 k2 = *(const float4*)&Ks[j + 2][d];
                float4 k3 = *(const float4*)&Ks[j + 3][d];
                s0 += qreg[d] * k0.x + qreg[d + 1] * k0.y + qreg[d + 2] * k0.z + qreg[d + 3] * k0.w;
                s1 += qreg[d] * k1.x + qreg[d + 1] * k1.y + qreg[d + 2] * k1.z + qreg[d + 3] * k1.w;
                s2 += qreg[d] * k2.x + qreg[d + 1] * k2.y + qreg[d + 2] * k2.z + qreg[d + 3] * k2.w;
                s3 += qreg[d] * k3.x + qreg[d + 1] * k3.y + qreg[d + 2] * k3.z + qreg[d + 3] * k3.w;
            }
            float mn = fmaxf(fmaxf(fmaxf(s0, s1), fmaxf(s2, s3)), m);
            float corr = __expf(m - mn);
            float p0 = __expf(s0 - mn), p1 = __expf(s1 - mn);
            float p2 = __expf(s2 - mn), p3 = __expf(s3 - mn);
            l = l * corr + p0 + p1 + p2 + p3;
            m = mn;
#pragma unroll
            for (int d = 0; d < 64; d += 4) {
                float4 v0 = *(const float4*)&Vs[j][d];
                float4 v1 = *(const float4*)&Vs[j + 1][d];
                float4 v2 = *(const float4*)&Vs[j + 2][d];
                float4 v3 = *(const float4*)&Vs[j + 3][d];
                o[d]     = o[d]     * corr + p0 * v0.x + p1 * v1.x + p2 * v2.x + p3 * v3.x;
                o[d + 1] = o[d + 1] * corr + p0 * v0.y + p1 * v1.y + p2 * v2.y + p3 * v3.y;
                o[d + 2] = o[d + 2] * corr + p0 * v0.z + p1 * v1.z + p2 * v2.z + p3 * v3.z;
                o[d + 3] = o[d + 3] * corr + p0 * v0.w + p1 * v1.w + p2 * v2.w + p3 * v3.w;
            }
        }
        for (; j < jmax; j++) {
            float s = 0.f;
#pragma unroll
            for (int d = 0; d < 64; d++) s += qreg[d] * Ks[j][d];
            float mn = fmaxf(m, s);
            float corr = __expf(m - mn);
            float p = __expf(s - mn);
            l = l * corr + p;
#pragma unroll
            for (int d = 0; d < 64; d++) o[d] = o[d] * corr + p * Vs[j][d];
            m = mn;
        }
        __syncthreads();
    }
    float invl = 1.f / l;
    size_t base = (size_t)qpos * DMODEL + (size_t)qh * HDIM;
#pragma unroll
    for (int d = 0; d < 64; d++) {
        float val = o[d] * invl;
        bf16 h, lo;
        bfsplit(val, h, lo);
        g_at_hi[base + d] = h;
        g_at_lo[base + d] = lo;
    }
}

__global__ __launch_bounds__(128) void router_kernel(
    const float* __restrict__ T, const float* __restrict__ Wr)
{
    int t = blockIdx.x;
    __shared__ float sred[128 * 8];
    float acc[8] = {};
    const float* tr = T + (size_t)t * DMODEL;
    for (int d = threadIdx.x; d < DMODEL; d += 128) {
        float x = tr[d];
        const float* wr = Wr + (size_t)d * NEXP;
#pragma unroll
        for (int e = 0; e < 8; e++) acc[e] += x * wr[e];
    }
#pragma unroll
    for (int e = 0; e < 8; e++) sred[threadIdx.x * 8 + e] = acc[e];
    __syncthreads();
    for (int s = 64; s > 0; s >>= 1) {
        if (threadIdx.x < s) {
#pragma unroll
            for (int e = 0; e < 8; e++)
                sred[threadIdx.x * 8 + e] += sred[(threadIdx.x + s) * 8 + e];
        }
        __syncthreads();
    }
    if (threadIdx.x == 0) {
        float best = -1e30f, second = -1e30f;
        int bi = 0, si = 0;
#pragma unroll
        for (int e = 0; e < 8; e++) {
            float v = sred[e];
            if (v > best)        { second = best; si = bi; best = v; bi = e; }
            else if (v > second) { second = v; si = e; }
        }
        float p0 = 1.f / (1.f + expf(second - best));
        g_topi[2 * t] = bi;  g_topi[2 * t + 1] = si;
        g_topw[2 * t] = p0;  g_topw[2 * t + 1] = 1.f - p0;
    }
}

__global__ __launch_bounds__(256) void assign_kernel()
{
    __shared__ int cnt[NEXP], base[NEXP + 1], cur[NEXP];
    if (threadIdx.x < NEXP) cnt[threadIdx.x] = 0;
    __syncthreads();
    for (int t = threadIdx.x; t < NTOK; t += 256) {
        atomicAdd(&cnt[g_topi[2 * t]], 1);
        atomicAdd(&cnt[g_topi[2 * t + 1]], 1);
    }
    __syncthreads();
    if (threadIdx.x == 0) {
        int s = 0;
        for (int e = 0; e < NEXP; e++) { base[e] = s; s += cnt[e]; }
        base[NEXP] = s;
    }
    __syncthreads();
    if (threadIdx.x < NEXP) cur[threadIdx.x] = base[threadIdx.x];
    if (threadIdx.x < NEXP + 1) g_off[threadIdx.x] = base[threadIdx.x];
    __syncthreads();
    for (int t = threadIdx.x; t < NTOK; t += 256) {
#pragma unroll
        for (int k = 0; k < 2; k++) {
            int e = g_topi[2 * t + k];
            int slot = atomicAdd(&cur[e], 1);
            g_slot_token[slot] = t;
            g_slot_of[2 * t + k] = slot;
        }
    }
}

__global__ __launch_bounds__(512) void silu_kernel()
{
    size_t i = ((size_t)blockIdx.x * 512 + threadIdx.x) * 4;
    float4 g = *(const float4*)(g_gate + i);
    float4 u = *(const float4*)(g_up + i);
    float a0 = g.x / (1.f + __expf(-g.x)) * u.x;
    float a1 = g.y / (1.f + __expf(-g.y)) * u.y;
    float a2 = g.z / (1.f + __expf(-g.z)) * u.z;
    float a3 = g.w / (1.f + __expf(-g.w)) * u.w;
    bf16 h0, l0, h1, l1, h2, l2, h3, l3;
    bfsplit(a0, h0, l0); bfsplit(a1, h1, l1);
    bfsplit(a2, h2, l2); bfsplit(a3, h3, l3);
    bf16* ph = g_act_hi + i;
    bf16* pl = g_act_lo + i;
    ph[0] = h0; ph[1] = h1; ph[2] = h2; ph[3] = h3;
    pl[0] = l0; pl[1] = l1; pl[2] = l2; pl[3] = l3;
}

__global__ __launch_bounds__(256) void combine_kernel(
    const float* __restrict__ h2, float* __restrict__ out)
{
    int t = blockIdx.x;
    int s0 = g_slot_of[2 * t], s1 = g_slot_of[2 * t + 1];
    float w0 = g_topw[2 * t], w1 = g_topw[2 * t + 1];
    const float* d0 = g_down + (size_t)s0 * DMODEL;
    const float* d1 = g_down + (size_t)s1 * DMODEL;
    const float* hr = h2 + (size_t)t * DMODEL;
    float* orow = out + (size_t)t * DMODEL;
    for (int d = threadIdx.x; d < DMODEL; d += 256)
        orow[d] = hr[d] + w0 * d0[d] + w1 * d1[d];
}

// ======================= launch =======================
extern "C" void kernel_launch(void* const* d_in, const int* in_sizes, int n_in,
                              void* d_out, int out_size)
{
    const float* hs   = (const float*)d_in[0];
    const int*   pos  = (const int*)d_in[1];
    const float* ln1w = (const float*)d_in[2];
    const float* Wq   = (const float*)d_in[3];
    const float* Wk   = (const float*)d_in[4];
    const float* Wv   = (const float*)d_in[5];
    const float* Wo   = (const float*)d_in[6];
    const float* ln2w = (const float*)d_in[7];
    const float* Wr   = (const float*)d_in[8];
    const float* W1   = (const float*)d_in[9];
    const float* W3   = (const float*)d_in[10];
    const float* W2   = (const float*)d_in[11];
    float* out = (float*)d_out;

    cudaFuncSetAttribute(tc_gemm, cudaFuncAttributeMaxDynamicSharedMemorySize, GEMM_SMEM);

    void* p;
    cudaGetSymbolAddress(&p, g_hn_hi);  bf16* hn_hi = (bf16*)p;
    cudaGetSymbolAddress(&p, g_hn_lo);  bf16* hn_lo = (bf16*)p;
    cudaGetSymbolAddress(&p, g_q);      float* q    = (float*)p;
    cudaGetSymbolAddress(&p, g_k);      float* k    = (float*)p;
    cudaGetSymbolAddress(&p, g_v);      float* v    = (float*)p;
    cudaGetSymbolAddress(&p, g_at_hi);  bf16* at_hi = (bf16*)p;
    cudaGetSymbolAddress(&p, g_at_lo);  bf16* at_lo = (bf16*)p;
    cudaGetSymbolAddress(&p, g_h2);     float* h2   = (float*)p;
    cudaGetSymbolAddress(&p, g_tn);     float* tn   = (float*)p;
    cudaGetSymbolAddress(&p, g_tn_hi);  bf16* tn_hi = (bf16*)p;
    cudaGetSymbolAddress(&p, g_tn_lo);  bf16* tn_lo = (bf16*)p;
    cudaGetSymbolAddress(&p, g_gate);   float* gate = (float*)p;
    cudaGetSymbolAddress(&p, g_up);     float* up   = (float*)p;
    cudaGetSymbolAddress(&p, g_act_hi); bf16* ac_hi = (bf16*)p;
    cudaGetSymbolAddress(&p, g_act_lo); bf16* ac_lo = (bf16*)p;
    cudaGetSymbolAddress(&p, g_down);   float* down = (float*)p;

    // 1. rmsnorm1 -> bf16 hi/lo
    rmsnorm_kernel<<<NTOK, 256>>>(hs, ln1w, nullptr, hn_hi, hn_lo);
    // 2. QKV projections
    tc_gemm<<<dim3(32, 8, 1), 512, GEMM_SMEM>>>(hn_hi, hn_lo, Wq, q, nullptr, NTOK, 2048, DMODEL, 0, 0);
    tc_gemm<<<dim3(8, 8, 1), 512, GEMM_SMEM>>>(hn_hi, hn_lo, Wk, k, nullptr, NTOK, 512, DMODEL, 0, 0);
    tc_gemm<<<dim3(8, 8, 1), 512, GEMM_SMEM>>>(hn_hi, hn_lo, Wv, v, nullptr, NTOK, 512, DMODEL, 0, 0);
    // 3. RoPE
    rope_kernel<<<dim3(SEQ, NHEAD), 32>>>(q, pos, NHEAD);
    rope_kernel<<<dim3(SEQ, NKV), 32>>>(k, pos, NKV);
    // 4. flash attention -> attn hi/lo
    flash_kernel<<<dim3(SEQ / 64, NKV), 256>>>();
    // 5. O projection + residual
    tc_gemm<<<dim3(32, 8, 1), 512, GEMM_SMEM>>>(at_hi, at_lo, Wo, h2, hs, NTOK, 2048, DMODEL, 0, 0);
    // 6. rmsnorm2
    rmsnorm_kernel<<<NTOK, 256>>>(h2, ln2w, tn, tn_hi, tn_lo);
    // 7-8. router + assignment
    router_kernel<<<NTOK, 128>>>(tn, Wr);
    assign_kernel<<<1, 256>>>();
    // 9. gate & up grouped GEMMs (gather)
    tc_gemm<<<dim3(112, 8, 8), 512, GEMM_SMEM>>>(tn_hi, tn_lo, W1, gate, nullptr, 0, FDIM, DMODEL, 1, 1);
    tc_gemm<<<dim3(112, 8, 8), 512, GEMM_SMEM>>>(tn_hi, tn_lo, W3, up, nullptr, 0, FDIM, DMODEL, 1, 1);
    // 10. silu(gate)*up -> act hi/lo
    silu_kernel<<<(int)((size_t)NSLOT * FDIM / 4 / 512), 512>>>();
    // 11. down grouped GEMM (slot-space A)
    tc_gemm<<<dim3(32, 8, 8), 512, GEMM_SMEM>>>(ac_hi, ac_lo, W2, down, nullptr, 0, DMODEL, FDIM, 1, 0);
    // 12. combine with residual
    combine_kernel<<<NTOK, 256>>>(h2, out);
}

// round 9
// speedup vs baseline: 1.7799x; 1.0155x over previous
#include <cuda_runtime.h>
#include <cuda_bf16.h>
#include <math.h>
#include <stdint.h>

#define SEQ    2048
#define DMODEL 2048
#define NHEAD  32
#define NKV    8
#define HDIM   64
#define NEXP   8
#define FDIM   7168
#define NTOK   2048
#define NSLOT  4096
#define EPSF   1e-5f

typedef __nv_bfloat16 bf16;

// ---------------- device scratch ----------------
__device__ bf16  g_hn_hi[NTOK * DMODEL], g_hn_lo[NTOK * DMODEL];
__device__ float g_q[NTOK * NHEAD * HDIM], g_k[NTOK * NKV * HDIM], g_v[NTOK * NKV * HDIM];
__device__ bf16  g_at_hi[NTOK * DMODEL], g_at_lo[NTOK * DMODEL];
__device__ float g_h2[NTOK * DMODEL], g_tn[NTOK * DMODEL];
__device__ bf16  g_tn_hi[NTOK * DMODEL], g_tn_lo[NTOK * DMODEL];
__device__ int   g_topi[NTOK * 2];
__device__ float g_topw[NTOK * 2];
__device__ int   g_slot_token[NSLOT], g_slot_of[NTOK * 2], g_off[NEXP + 1];
__device__ float g_gate[(size_t)NSLOT * FDIM], g_up[(size_t)NSLOT * FDIM];
__device__ bf16  g_act_hi[(size_t)NSLOT * FDIM], g_act_lo[(size_t)NSLOT * FDIM];
__device__ float g_down[(size_t)NSLOT * DMODEL];

// ---------------- helpers ----------------
__device__ __forceinline__ uint32_t smem_u32(const void* p) {
    uint32_t a;
    asm("{ .reg .u64 t; cvta.to.shared.u64 t, %1; cvt.u32.u64 %0, t; }" : "=r"(a) : "l"(p));
    return a;
}
__device__ __forceinline__ void ldsm4(uint32_t* r, uint32_t addr) {
    asm volatile("ldmatrix.sync.aligned.m8n8.x4.shared.b16 {%0,%1,%2,%3}, [%4];"
                 : "=r"(r[0]), "=r"(r[1]), "=r"(r[2]), "=r"(r[3]) : "r"(addr));
}
__device__ __forceinline__ void mma16816(float* c, const uint32_t* a, const uint32_t* b) {
    asm volatile(
        "mma.sync.aligned.m16n8k16.row.col.f32.bf16.bf16.f32 "
        "{%0,%1,%2,%3}, {%4,%5,%6,%7}, {%8,%9}, {%0,%1,%2,%3};"
        : "+f"(c[0]), "+f"(c[1]), "+f"(c[2]), "+f"(c[3])
        : "r"(a[0]), "r"(a[1]), "r"(a[2]), "r"(a[3]), "r"(b[0]), "r"(b[1]));
}
__device__ __forceinline__ void cp16(uint32_t dst, const void* src) {
    asm volatile("cp.async.cg.shared.global [%0], [%1], 16;" :: "r"(dst), "l"(src));
}
__device__ __forceinline__ void cp_commit() { asm volatile("cp.async.commit_group;"); }
__device__ __forceinline__ void cp_wait0()  { asm volatile("cp.async.wait_group 0;"); }
__device__ __forceinline__ void bfsplit(float x, bf16& h, bf16& l) {
    h = __float2bfloat16_rn(x);
    l = __float2bfloat16_rn(x - __bfloat162float(h));
}

// ---------------- tc_gemm geometry (proven Round-5 config) ----------------
#define BM 256
#define BN 64
#define KC 64
#define ASTR 72
#define BSTR 72
#define OFF_AH(b) (1024u + (b) * 36864u)
#define OFF_AL(b) (1024u + 73728u + (b) * 36864u)
#define OFF_BH(b) (1024u + 147456u + (b) * 9216u)
#define OFF_BL(b) (1024u + 165888u + (b) * 9216u)
#define GEMM_SMEM 185344

__device__ __forceinline__ void gemm_issueA(uint32_t sb, int buf,
    const bf16* __restrict__ Ahi, const bf16* __restrict__ Alo,
    const int* rowg, int K, int k0, int tid)
{
#pragma unroll
    for (int it = 0; it < 4; it++) {
        int idx = tid + it * 512;
        int row = idx >> 3, seg = idx & 7;
        size_t goff = (size_t)rowg[row] * K + k0 + seg * 8;
        uint32_t soff = ((uint32_t)row * ASTR + (uint32_t)seg * 8) * 2u;
        cp16(sb + OFF_AH(buf) + soff, Ahi + goff);
        cp16(sb + OFF_AL(buf) + soff, Alo + goff);
    }
}
__device__ __forceinline__ void gemm_ldgB(const float* __restrict__ Bp, int N, int k0,
                                          int n0, int bn, int bk, float* bst)
{
    const float* p = Bp + (size_t)(k0 + bk) * N + n0 + bn;
#pragma unroll
    for (int j = 0; j < 8; j++) bst[j] = p[(size_t)j * N];
}
__device__ __forceinline__ void gemm_stsB(char* sm, int buf, int bn, int bk, const float* bst)
{
    uint32_t h[4], l[4];
#pragma unroll
    for (int j = 0; j < 4; j++) {
        bf16 h0, l0, h1, l1;
        bfsplit(bst[2 * j], h0, l0);
        bfsplit(bst[2 * j + 1], h1, l1);
        h[j] = (uint32_t)*(unsigned short*)&h0 | ((uint32_t)*(unsigned short*)&h1 << 16);
        l[j] = (uint32_t)*(unsigned short*)&l0 | ((uint32_t)*(unsigned short*)&l1 << 16);
    }
    uint32_t off = ((uint32_t)bn * BSTR + (uint32_t)bk) * 2u;
    *(uint4*)(sm + OFF_BH(buf) + off) = make_uint4(h[0], h[1], h[2], h[3]);
    *(uint4*)(sm + OFF_BL(buf) + off) = make_uint4(l[0], l[1], l[2], l[3]);
}
__device__ __forceinline__ void gemm_compute(uint32_t sb, char* sm, int buf,
                                             int wm, int wn, int lane, float acc[4][2][4])
{
    bf16* Bh = (bf16*)(sm + OFF_BH(buf));
    bf16* Bl = (bf16*)(sm + OFF_BL(buf));
    uint32_t ah_s = sb + OFF_AH(buf), al_s = sb + OFF_AL(buf);
#pragma unroll
    for (int kf = 0; kf < 4; kf++) {
        uint32_t bh[2][2], bl[2][2];
        int kb = kf * 16 + (lane & 3) * 2;
#pragma unroll
        for (int nf = 0; nf < 2; nf++) {
            int n = wn * 16 + nf * 8 + (lane >> 2);
            bh[nf][0] = *(const uint32_t*)&Bh[n * BSTR + kb];
            bh[nf][1] = *(const uint32_t*)&Bh[n * BSTR + kb + 8];
            bl[nf][0] = *(const uint32_t*)&Bl[n * BSTR + kb];
            bl[nf][1] = *(const uint32_t*)&Bl[n * BSTR + kb + 8];
        }
#pragma unroll
        for (int mf = 0; mf < 4; mf++) {
            int r = wm * 64 + mf * 16 + (lane & 15);
            uint32_t boff = ((uint32_t)r * ASTR + (uint32_t)(kf * 16 + (lane >> 4) * 8)) * 2u;
            uint32_t ah[4], al[4];
            ldsm4(ah, ah_s + boff);
            ldsm4(al, al_s + boff);
#pragma unroll
            for (int nf = 0; nf < 2; nf++) {
                mma16816(acc[mf][nf], ah, bh[nf]);
                mma16816(acc[mf][nf], ah, bl[nf]);
                mma16816(acc[mf][nf], al, bh[nf]);
            }
        }
    }
}

// ======================= HMMA GEMM, cp.async double-buffered =======================
__global__ __launch_bounds__(512, 1) void tc_gemm(
    const bf16* __restrict__ Ahi, const bf16* __restrict__ Alo,
    const float* __restrict__ B, float* __restrict__ C, const float* __restrict__ res,
    int M, int N, int K, int grouped, int gather)
{
    int e = blockIdx.z;
    int rbeg = 0, rows = M;
    if (grouped) { rbeg = g_off[e]; rows = g_off[e + 1] - rbeg; }
    int mg0 = blockIdx.y * BM;
    if (mg0 >= rows) return;
    int n0 = blockIdx.x * BN;
    const float* Bp = B + (size_t)e * K * N;

    extern __shared__ char sm[];
    uint32_t sb = smem_u32(sm);
    int* rowg = (int*)sm;
    int tid = threadIdx.x, lane = tid & 31, warp = tid >> 5;
    int wm = warp >> 2, wn = warp & 3;

    for (int r = tid; r < BM; r += 512) {
        int m = mg0 + r, rg;
        if (gather)       rg = (m < rows) ? g_slot_token[rbeg + m] : 0;
        else if (grouped) rg = (m < rows) ? (rbeg + m) : rbeg;
        else              rg = (m < rows) ? m : 0;
        rowg[r] = rg;
    }
    __syncthreads();

    float acc[4][2][4];
#pragma unroll
    for (int a = 0; a < 4; a++)
#pragma unroll
        for (int b = 0; b < 2; b++)
#pragma unroll
            for (int c = 0; c < 4; c++) acc[a][b][c] = 0.f;

    int bn = tid & 63, bk = (tid >> 6) * 8;
    float bst[8];
    int NC = K / KC;

    // prologue: chunk 0
    gemm_issueA(sb, 0, Ahi, Alo, rowg, K, 0, tid);
    cp_commit();
    gemm_ldgB(Bp, N, 0, n0, bn, bk, bst);
    cp_wait0();
    __syncthreads();
    gemm_stsB(sm, 0, bn, bk, bst);
    __syncthreads();

    for (int ch = 0; ch < NC; ch++) {
        int buf = ch & 1;
        if (ch + 1 < NC) {
            gemm_issueA(sb, buf ^ 1, Ahi, Alo, rowg, K, (ch + 1) * KC, tid);
            cp_commit();
            gemm_ldgB(Bp, N, (ch + 1) * KC, n0, bn, bk, bst);
        }
        gemm_compute(sb, sm, buf, wm, wn, lane, acc);
        if (ch + 1 < NC) {
            cp_wait0();
            __syncthreads();
            gemm_stsB(sm, buf ^ 1, bn, bk, bst);
            __syncthreads();
        }
    }

    // writeback
#pragma unroll
    for (int mf = 0; mf < 4; mf++) {
#pragma unroll
        for (int half = 0; half < 2; half++) {
            int m = mg0 + wm * 64 + mf * 16 + (lane >> 2) + half * 8;
            if (m < rows) {
                size_t crow = (size_t)(rbeg + m);
                float* cp = C + crow * N + n0 + wn * 16 + (lane & 3) * 2;
                const float* rp = res ? res + (size_t)m * N + n0 + wn * 16 + (lane & 3) * 2 : nullptr;
#pragma unroll
                for (int nf = 0; nf < 2; nf++) {
                    float2 v;
                    v.x = acc[mf][nf][half * 2];
                    v.y = acc[mf][nf][half * 2 + 1];
                    if (rp) { v.x += rp[nf * 8]; v.y += rp[nf * 8 + 1]; }
                    *(float2*)(cp + nf * 8) = v;
                }
            }
        }
    }
}

// ======================= small kernels =======================
__global__ __launch_bounds__(256) void rmsnorm_kernel(
    const float* __restrict__ x, const float* __restrict__ w,
    float* __restrict__ yf, bf16* __restrict__ yh, bf16* __restrict__ yl)
{
    int row = blockIdx.x;
    const float* xr = x + (size_t)row * DMODEL;
    __shared__ float red[256];
    float ss = 0.f;
    const float4* x4 = (const float4*)xr;
    for (int i = threadIdx.x; i < DMODEL / 4; i += 256) {
        float4 v = x4[i];
        ss += v.x * v.x + v.y * v.y + v.z * v.z + v.w * v.w;
    }
    red[threadIdx.x] = ss;
    __syncthreads();
    for (int s = 128; s > 0; s >>= 1) {
        if (threadIdx.x < s) red[threadIdx.x] += red[threadIdx.x + s];
        __syncthreads();
    }
    float inv = rsqrtf(red[0] / (float)DMODEL + EPSF);
    for (int i = threadIdx.x; i < DMODEL; i += 256) {
        float val = xr[i] * inv * w[i];
        if (yf) yf[(size_t)row * DMODEL + i] = val;
        bf16 h, l;
        bfsplit(val, h, l);
        yh[(size_t)row * DMODEL + i] = h;
        yl[(size_t)row * DMODEL + i] = l;
    }
}

__global__ void rope_kernel(float* __restrict__ x, const int* __restrict__ pos, int nheads)
{
    int s = blockIdx.x, h = blockIdx.y, i = threadIdx.x;
    float p = (float)pos[s];
    float inv = expf(-((float)(2 * i) / 64.f) * 13.815510557964274f);
    float ang = p * inv;
    float sn, cs;
    sincosf(ang, &sn, &cs);
    float* xp = x + ((size_t)s * nheads + h) * HDIM;
    float x1 = xp[i], x2 = xp[i + 32];
    xp[i]      = x1 * cs - x2 * sn;
    xp[i + 32] = x2 * cs + x1 * sn;
}

// ---------------- flash attention: 2-way dim split, q-tile 32 ----------------
__global__ __launch_bounds__(256, 3) void flash_kernel()
{
    int bq = gridDim.x - 1 - blockIdx.x;   // largest tiles first
    int kvh = blockIdx.y;
    int tid = threadIdx.x;
    int w = tid >> 5, l = tid & 31;
    int half = l >> 4;
    int unit = w * 16 + (l & 15);          // 0..127 = 32q x 4h
    int ql = unit & 31, sub = unit >> 5;
    int qpos = bq * 32 + ql;
    int qh = kvh * 4 + sub;
    __shared__ __align__(16) float Ks[32][64];
    __shared__ __align__(16) float Vs[32][64];
    float qreg[32], o[32];
    const float4* qp = (const float4*)(g_q + ((size_t)qpos * NHEAD + qh) * HDIM + half * 32);
#pragma unroll
    for (int d4 = 0; d4 < 8; d4++) {
        float4 v = qp[d4];
        qreg[4 * d4] = v.x * 0.125f; qreg[4 * d4 + 1] = v.y * 0.125f;
        qreg[4 * d4 + 2] = v.z * 0.125f; qreg[4 * d4 + 3] = v.w * 0.125f;
        o[4 * d4] = 0.f; o[4 * d4 + 1] = 0.f; o[4 * d4 + 2] = 0.f; o[4 * d4 + 3] = 0.f;
    }
    float m = -INFINITY, lsum = 0.f;
    int kend = bq * 32 + 32;
    int qmax_w = bq * 32 + (w & 1) * 16 + 15;   // max qpos in this warp
    for (int kt = 0; kt < kend; kt += 32) {
        for (int i = tid; i < 32 * 16; i += 256) {
            int j = i >> 4, d4 = (i & 15) * 4;
            *(float4*)&Ks[j][d4] = *(const float4*)(g_k + ((size_t)(kt + j) * NKV + kvh) * HDIM + d4);
            *(float4*)&Vs[j][d4] = *(const float4*)(g_v + ((size_t)(kt + j) * NKV + kvh) * HDIM + d4);
        }
        __syncthreads();
        int jw = qmax_w - kt + 1;
        if (jw > 32) jw = 32;
        for (int j = 0; j < jw; j += 4) {
            float s0 = 0.f, s1 = 0.f, s2 = 0.f, s3 = 0.f;
            int hb = half * 32;
#pragma unroll
            for (int d = 0; d < 32; d += 4) {
                float4 k0 = *(const float4*)&Ks[j][hb + d];
                float4 k1 = *(const float4*)&Ks[j + 1][hb + d];
                float4 k2 = *(const float4*)&Ks[j + 2][hb + d];
                float4 k3 = *(const float4*)&Ks[j + 3][hb + d];
                s0 += qreg[d] * k0.x + qreg[d + 1] * k0.y + qreg[d + 2] * k0.z + qreg[d + 3] * k0.w;
                s1 += qreg[d] * k1.x + qreg[d + 1] * k1.y + qreg[d + 2] * k1.z + qreg[d + 3] * k1.w;
                s2 += qreg[d] * k2.x + qreg[d + 1] * k2.y + qreg[d + 2] * k2.z + qreg[d + 3] * k2.w;
                s3 += qreg[d] * k3.x + qreg[d + 1] * k3.y + qreg[d + 2] * k3.z + qreg[d + 3] * k3.w;
            }
            s0 += __shfl_xor_sync(0xFFFFFFFFu, s0, 16);
            s1 += __shfl_xor_sync(0xFFFFFFFFu, s1, 16);
            s2 += __shfl_xor_sync(0xFFFFFFFFu, s2, 16);
            s3 += __shfl_xor_sync(0xFFFFFFFFu, s3, 16);
            if (kt + j     > qpos) s0 = -1e30f;
            if (kt + j + 1 > qpos) s1 = -1e30f;
            if (kt + j + 2 > qpos) s2 = -1e30f;
            if (kt + j + 3 > qpos) s3 = -1e30f;
            float mn = fmaxf(fmaxf(fmaxf(s0, s1), fmaxf(s2, s3)), m);
            float corr = __expf(m - mn);
            float p0 = __expf(s0 - mn), p1 = __expf(s1 - mn);
            float p2 = __expf(s2 - mn), p3 = __expf(s3 - mn);
            lsum = lsum * corr + p0 + p1 + p2 + p3;
            m = mn;
#pragma unroll
            for (int d = 0; d < 32; d += 4) {
                float4 v0 = *(const float4*)&Vs[j][hb + d];
                float4 v1 = *(const float4*)&Vs[j + 1][hb + d];
                float4 v2 = *(const float4*)&Vs[j + 2][hb + d];
                float4 v3 = *(const float4*)&Vs[j + 3][hb + d];
                o[d]     = o[d]     * corr + p0 * v0.x + p1 * v1.x + p2 * v2.x + p3 * v3.x;
                o[d + 1] = o[d + 1] * corr + p0 * v0.y + p1 * v1.y + p2 * v2.y + p3 * v3.y;
                o[d + 2] = o[d + 2] * corr + p0 * v0.z + p1 * v1.z + p2 * v2.z + p3 * v3.z;
                o[d + 3] = o[d + 3] * corr + p0 * v0.w + p1 * v1.w + p2 * v2.w + p3 * v3.w;
            }
        }
        __syncthreads();
    }
    float invl = 1.f / lsum;
    size_t base = (size_t)qpos * DMODEL + (size_t)qh * HDIM + half * 32;
#pragma unroll
    for (int d = 0; d < 32; d++) {
        float val = o[d] * invl;
        bf16 h, lo;
        bfsplit(val, h, lo);
        g_at_hi[base + d] = h;
        g_at_lo[base + d] = lo;
    }
}

__global__ __launch_bounds__(128) void router_kernel(
    const float* __restrict__ T, const float* __restrict__ Wr)
{
    int t = blockIdx.x;
    __shared__ float sred[128 * 8];
    float acc[8] = {};
    const float* tr = T + (size_t)t * DMODEL;
    for (int d = threadIdx.x; d < DMODEL; d += 128) {
        float x = tr[d];
        const float* wr = Wr + (size_t)d * NEXP;
#pragma unroll
        for (int e = 0; e < 8; e++) acc[e] += x * wr[e];
    }
#pragma unroll
    for (int e = 0; e < 8; e++) sred[threadIdx.x * 8 + e] = acc[e];
    __syncthreads();
    for (int s = 64; s > 0; s >>= 1) {
        if (threadIdx.x < s) {
#pragma unroll
            for (int e = 0; e < 8; e++)
                sred[threadIdx.x * 8 + e] += sred[(threadIdx.x + s) * 8 + e];
        }
        __syncthreads();
    }
    if (threadIdx.x == 0) {
        float best = -1e30f, second = -1e30f;
        int bi = 0, si = 0;
#pragma unroll
        for (int e = 0; e < 8; e++) {
            float v = sred[e];
            if (v > best)        { second = best; si = bi; best = v; bi = e; }
            else if (v > second) { second = v; si = e; }
        }
        float p0 = 1.f / (1.f + expf(second - best));
        g_topi[2 * t] = bi;  g_topi[2 * t + 1] = si;
        g_topw[2 * t] = p0;  g_topw[2 * t + 1] = 1.f - p0;
    }
}

__global__ __launch_bounds__(256) void assign_kernel()
{
    __shared__ int cnt[NEXP], base[NEXP + 1], cur[NEXP];
    if (threadIdx.x < NEXP) cnt[threadIdx.x] = 0;
    __syncthreads();
    for (int t = threadIdx.x; t < NTOK; t += 256) {
        atomicAdd(&cnt[g_topi[2 * t]], 1);
        atomicAdd(&cnt[g_topi[2 * t + 1]], 1);
    }
    __syncthreads();
    if (threadIdx.x == 0) {
        int s = 0;
        for (int e = 0; e < NEXP; e++) { base[e] = s; s += cnt[e]; }
        base[NEXP] = s;
    }
    __syncthreads();
    if (threadIdx.x < NEXP) cur[threadIdx.x] = base[threadIdx.x];
    if (threadIdx.x < NEXP + 1) g_off[threadIdx.x] = base[threadIdx.x];
    __syncthreads();
    for (int t = threadIdx.x; t < NTOK; t += 256) {
#pragma unroll
        for (int k = 0; k < 2; k++) {
            int e = g_topi[2 * t + k];
            int slot = atomicAdd(&cur[e], 1);
            g_slot_token[slot] = t;
            g_slot_of[2 * t + k] = slot;
        }
    }
}

__global__ __launch_bounds__(512) void silu_kernel()
{
    size_t i = ((size_t)blockIdx.x * 512 + threadIdx.x) * 4;
    float4 g = *(const float4*)(g_gate + i);
    float4 u = *(const float4*)(g_up + i);
    float a0 = g.x / (1.f + __expf(-g.x)) * u.x;
    float a1 = g.y / (1.f + __expf(-g.y)) * u.y;
    float a2 = g.z / (1.f + __expf(-g.z)) * u.z;
    float a3 = g.w / (1.f + __expf(-g.w)) * u.w;
    bf16 h0, l0, h1, l1, h2, l2, h3, l3;
    bfsplit(a0, h0, l0); bfsplit(a1, h1, l1);
    bfsplit(a2, h2, l2); bfsplit(a3, h3, l3);
    bf16* ph = g_act_hi + i;
    bf16* pl = g_act_lo + i;
    ph[0] = h0; ph[1] = h1; ph[2] = h2; ph[3] = h3;
    pl[0] = l0; pl[1] = l1; pl[2] = l2; pl[3] = l3;
}

__global__ __launch_bounds__(256) void combine_kernel(
    const float* __restrict__ h2, float* __restrict__ out)
{
    int t = blockIdx.x;
    int s0 = g_slot_of[2 * t], s1 = g_slot_of[2 * t + 1];
    float w0 = g_topw[2 * t], w1 = g_topw[2 * t + 1];
    const float* d0 = g_down + (size_t)s0 * DMODEL;
    const float* d1 = g_down + (size_t)s1 * DMODEL;
    const float* hr = h2 + (size_t)t * DMODEL;
    float* orow = out + (size_t)t * DMODEL;
    for (int d = threadIdx.x; d < DMODEL; d += 256)
        orow[d] = hr[d] + w0 * d0[d] + w1 * d1[d];
}

// ======================= launch =======================
extern "C" void kernel_launch(void* const* d_in, const int* in_sizes, int n_in,
                              void* d_out, int out_size)
{
    const float* hs   = (const float*)d_in[0];
    const int*   pos  = (const int*)d_in[1];
    const float* ln1w = (const float*)d_in[2];
    const float* Wq   = (const float*)d_in[3];
    const float* Wk   = (const float*)d_in[4];
    const float* Wv   = (const float*)d_in[5];
    const float* Wo   = (const float*)d_in[6];
    const float* ln2w = (const float*)d_in[7];
    const float* Wr   = (const float*)d_in[8];
    const float* W1   = (const float*)d_in[9];
    const float* W3   = (const float*)d_in[10];
    const float* W2   = (const float*)d_in[11];
    float* out = (float*)d_out;

    cudaFuncSetAttribute(tc_gemm, cudaFuncAttributeMaxDynamicSharedMemorySize, GEMM_SMEM);

    void* p;
    cudaGetSymbolAddress(&p, g_hn_hi);  bf16* hn_hi = (bf16*)p;
    cudaGetSymbolAddress(&p, g_hn_lo);  bf16* hn_lo = (bf16*)p;
    cudaGetSymbolAddress(&p, g_q);      float* q    = (float*)p;
    cudaGetSymbolAddress(&p, g_k);      float* k    = (float*)p;
    cudaGetSymbolAddress(&p, g_v);      float* v    = (float*)p;
    cudaGetSymbolAddress(&p, g_at_hi);  bf16* at_hi = (bf16*)p;
    cudaGetSymbolAddress(&p, g_at_lo);  bf16* at_lo = (bf16*)p;
    cudaGetSymbolAddress(&p, g_h2);     float* h2   = (float*)p;
    cudaGetSymbolAddress(&p, g_tn);     float* tn   = (float*)p;
    cudaGetSymbolAddress(&p, g_tn_hi);  bf16* tn_hi = (bf16*)p;
    cudaGetSymbolAddress(&p, g_tn_lo);  bf16* tn_lo = (bf16*)p;
    cudaGetSymbolAddress(&p, g_gate);   float* gate = (float*)p;
    cudaGetSymbolAddress(&p, g_up);     float* up   = (float*)p;
    cudaGetSymbolAddress(&p, g_act_hi); bf16* ac_hi = (bf16*)p;
    cudaGetSymbolAddress(&p, g_act_lo); bf16* ac_lo = (bf16*)p;
    cudaGetSymbolAddress(&p, g_down);   float* down = (float*)p;

    // 1. rmsnorm1 -> bf16 hi/lo
    rmsnorm_kernel<<<NTOK, 256>>>(hs, ln1w, nullptr, hn_hi, hn_lo);
    // 2. QKV projections
    tc_gemm<<<dim3(32, 8, 1), 512, GEMM_SMEM>>>(hn_hi, hn_lo, Wq, q, nullptr, NTOK, 2048, DMODEL, 0, 0);
    tc_gemm<<<dim3(8, 8, 1), 512, GEMM_SMEM>>>(hn_hi, hn_lo, Wk, k, nullptr, NTOK, 512, DMODEL, 0, 0);
    tc_gemm<<<dim3(8, 8, 1), 512, GEMM_SMEM>>>(hn_hi, hn_lo, Wv, v, nullptr, NTOK, 512, DMODEL, 0, 0);
    // 3. RoPE
    rope_kernel<<<dim3(SEQ, NHEAD), 32>>>(q, pos, NHEAD);
    rope_kernel<<<dim3(SEQ, NKV), 32>>>(k, pos, NKV);
    // 4. flash attention -> attn hi/lo
    flash_kernel<<<dim3(SEQ / 32, NKV), 256>>>();
    // 5. O projection + residual
    tc_gemm<<<dim3(32, 8, 1), 512, GEMM_SMEM>>>(at_hi, at_lo, Wo, h2, hs, NTOK, 2048, DMODEL, 0, 0);
    // 6. rmsnorm2
    rmsnorm_kernel<<<NTOK, 256>>>(h2, ln2w, tn, tn_hi, tn_lo);
    // 7-8. router + assignment
    router_kernel<<<NTOK, 128>>>(tn, Wr);
    assign_kernel<<<1, 256>>>();
    // 9. gate & up grouped GEMMs (gather)
    tc_gemm<<<dim3(112, 8, 8), 512, GEMM_SMEM>>>(tn_hi, tn_lo, W1, gate, nullptr, 0, FDIM, DMODEL, 1, 1);
    tc_gemm<<<dim3(112, 8, 8), 512, GEMM_SMEM>>>(tn_hi, tn_lo, W3, up, nullptr, 0, FDIM, DMODEL, 1, 1);
    // 10. silu(gate)*up -> act hi/lo
    silu_kernel<<<(int)((size_t)NSLOT * FDIM / 4 / 512), 512>>>();
    // 11. down grouped GEMM (slot-space A)
    tc_gemm<<<dim3(32, 8, 8), 512, GEMM_SMEM>>>(ac_hi, ac_lo, W2, down, nullptr, 0, DMODEL, FDIM, 1, 0);
    // 12. combine with residual
    combine_kernel<<<NTOK, 256>>>(h2, out);
}

// round 10
// speedup vs baseline: 2.2089x; 1.2411x over previous
#include <cuda_runtime.h>
#include <cuda_bf16.h>
#include <math.h>
#include <stdint.h>

#define SEQ    2048
#define DMODEL 2048
#define NHEAD  32
#define NKV    8
#define HDIM   64
#define NEXP   8
#define FDIM   7168
#define NTOK   2048
#define NSLOT  4096
#define EPSF   1e-5f

typedef __nv_bfloat16 bf16;

// ---------------- device scratch ----------------
__device__ bf16  g_hn_hi[NTOK * DMODEL], g_hn_lo[NTOK * DMODEL];
__device__ float g_q[NTOK * NHEAD * HDIM], g_k[NTOK * NKV * HDIM], g_v[NTOK * NKV * HDIM];
__device__ bf16  g_at_hi[NTOK * DMODEL], g_at_lo[NTOK * DMODEL];
__device__ float g_h2[NTOK * DMODEL], g_tn[NTOK * DMODEL];
__device__ bf16  g_tn_hi[NTOK * DMODEL], g_tn_lo[NTOK * DMODEL];
__device__ int   g_topi[NTOK * 2];
__device__ float g_topw[NTOK * 2];
__device__ int   g_slot_token[NSLOT], g_slot_of[NTOK * 2], g_off[NEXP + 1];
__device__ float g_gate[(size_t)NSLOT * FDIM], g_up[(size_t)NSLOT * FDIM];
__device__ bf16  g_act_hi[(size_t)NSLOT * FDIM], g_act_lo[(size_t)NSLOT * FDIM];
__device__ float g_down[(size_t)NSLOT * DMODEL];

// ---------------- helpers ----------------
__device__ __forceinline__ uint32_t smem_u32(const void* p) {
    uint32_t a;
    asm("{ .reg .u64 t; cvta.to.shared.u64 t, %1; cvt.u32.u64 %0, t; }" : "=r"(a) : "l"(p));
    return a;
}
__device__ __forceinline__ void ldsm4(uint32_t* r, uint32_t addr) {
    asm volatile("ldmatrix.sync.aligned.m8n8.x4.shared.b16 {%0,%1,%2,%3}, [%4];"
                 : "=r"(r[0]), "=r"(r[1]), "=r"(r[2]), "=r"(r[3]) : "r"(addr));
}
__device__ __forceinline__ void mma16816(float* c, const uint32_t* a, const uint32_t* b) {
    asm volatile(
        "mma.sync.aligned.m16n8k16.row.col.f32.bf16.bf16.f32 "
        "{%0,%1,%2,%3}, {%4,%5,%6,%7}, {%8,%9}, {%0,%1,%2,%3};"
        : "+f"(c[0]), "+f"(c[1]), "+f"(c[2]), "+f"(c[3])
        : "r"(a[0]), "r"(a[1]), "r"(a[2]), "r"(a[3]), "r"(b[0]), "r"(b[1]));
}
__device__ __forceinline__ void cp16(uint32_t dst, const void* src) {
    asm volatile("cp.async.cg.shared.global [%0], [%1], 16;" :: "r"(dst), "l"(src));
}
__device__ __forceinline__ void cp_commit() { asm volatile("cp.async.commit_group;"); }
__device__ __forceinline__ void cp_wait0()  { asm volatile("cp.async.wait_group 0;"); }
__device__ __forceinline__ void bfsplit(float x, bf16& h, bf16& l) {
    h = __float2bfloat16_rn(x);
    l = __float2bfloat16_rn(x - __bfloat162float(h));
}

// ---------------- tc_gemm geometry: BM=128, BN=64, KC=32, 256 thr, 3 CTAs/SM ----------------
#define BM 128
#define BN 64
#define KC 32
#define ASTR 40
#define BSTR 40
// smem: rowg 512B | AH0 AL0 | AH1 AL1 (2 x 20480) | BH0 BL0 | BH1 BL1 (2 x 10240)
#define OFF_AH(b) (512u + (b) * 20480u)
#define OFF_AL(b) (512u + 10240u + (b) * 20480u)
#define OFF_BH(b) (41472u + (b) * 10240u)
#define OFF_BL(b) (41472u + 5120u + (b) * 10240u)
#define GEMM_SMEM 61952

__device__ __forceinline__ void gemm_issueA(uint32_t sb, int buf,
    const bf16* __restrict__ Ahi, const bf16* __restrict__ Alo,
    const int* rowg, int K, int k0, int tid)
{
#pragma unroll
    for (int it = 0; it < 2; it++) {
        int idx = tid + it * 256;          // 0..511
        int row = idx >> 2, seg = idx & 3;
        size_t goff = (size_t)rowg[row] * K + k0 + seg * 8;
        uint32_t soff = ((uint32_t)row * ASTR + (uint32_t)seg * 8) * 2u;
        cp16(sb + OFF_AH(buf) + soff, Ahi + goff);
        cp16(sb + OFF_AL(buf) + soff, Alo + goff);
    }
}
__device__ __forceinline__ void gemm_ldgB(const float* __restrict__ Bp, int N, int k0,
                                          int n0, int bn, int bk, float* bst)
{
    const float* p = Bp + (size_t)(k0 + bk) * N + n0 + bn;
#pragma unroll
    for (int j = 0; j < 8; j++) bst[j] = p[(size_t)j * N];
}
__device__ __forceinline__ void gemm_stsB(char* sm, int buf, int bn, int bk, const float* bst)
{
    uint32_t h[4], l[4];
#pragma unroll
    for (int j = 0; j < 4; j++) {
        bf16 h0, l0, h1, l1;
        bfsplit(bst[2 * j], h0, l0);
        bfsplit(bst[2 * j + 1], h1, l1);
        h[j] = (uint32_t)*(unsigned short*)&h0 | ((uint32_t)*(unsigned short*)&h1 << 16);
        l[j] = (uint32_t)*(unsigned short*)&l0 | ((uint32_t)*(unsigned short*)&l1 << 16);
    }
    uint32_t off = ((uint32_t)bn * BSTR + (uint32_t)bk) * 2u;
    *(uint4*)(sm + OFF_BH(buf) + off) = make_uint4(h[0], h[1], h[2], h[3]);
    *(uint4*)(sm + OFF_BL(buf) + off) = make_uint4(l[0], l[1], l[2], l[3]);
}
__device__ __forceinline__ void gemm_compute(uint32_t sb, char* sm, int buf,
                                             int wm, int wn, int lane, float acc[4][2][4])
{
    bf16* Bh = (bf16*)(sm + OFF_BH(buf));
    bf16* Bl = (bf16*)(sm + OFF_BL(buf));
    uint32_t ah_s = sb + OFF_AH(buf), al_s = sb + OFF_AL(buf);
#pragma unroll
    for (int kf = 0; kf < 2; kf++) {
        uint32_t bh[2][2], bl[2][2];
        int kb = kf * 16 + (lane & 3) * 2;
#pragma unroll
        for (int nf = 0; nf < 2; nf++) {
            int n = wn * 16 + nf * 8 + (lane >> 2);
            bh[nf][0] = *(const uint32_t*)&Bh[n * BSTR + kb];
            bh[nf][1] = *(const uint32_t*)&Bh[n * BSTR + kb + 8];
            bl[nf][0] = *(const uint32_t*)&Bl[n * BSTR + kb];
            bl[nf][1] = *(const uint32_t*)&Bl[n * BSTR + kb + 8];
        }
#pragma unroll
        for (int mf = 0; mf < 4; mf++) {
            int r = wm * 64 + mf * 16 + (lane & 15);
            uint32_t boff = ((uint32_t)r * ASTR + (uint32_t)(kf * 16 + (lane >> 4) * 8)) * 2u;
            uint32_t ah[4], al[4];
            ldsm4(ah, ah_s + boff);
            ldsm4(al, al_s + boff);
#pragma unroll
            for (int nf = 0; nf < 2; nf++) {
                mma16816(acc[mf][nf], ah, bh[nf]);
                mma16816(acc[mf][nf], ah, bl[nf]);
                mma16816(acc[mf][nf], al, bh[nf]);
            }
        }
    }
}

// ======================= HMMA GEMM, cp.async double-buffered =======================
// 256 thr, warp grid 2(wm) x 4(wn); warp tile 64x16 (mf<4). BM=128 fully covered.
__global__ __launch_bounds__(256, 3) void tc_gemm(
    const bf16* __restrict__ Ahi, const bf16* __restrict__ Alo,
    const float* __restrict__ B, float* __restrict__ C, const float* __restrict__ res,
    int M, int N, int K, int grouped, int gather)
{
    int e = blockIdx.z;
    int rbeg = 0, rows = M;
    if (grouped) { rbeg = g_off[e]; rows = g_off[e + 1] - rbeg; }
    int mg0 = blockIdx.y * BM;
    if (mg0 >= rows) return;
    int n0 = blockIdx.x * BN;
    const float* Bp = B + (size_t)e * K * N;

    extern __shared__ char sm[];
    uint32_t sb = smem_u32(sm);
    int* rowg = (int*)sm;
    int tid = threadIdx.x, lane = tid & 31, warp = tid >> 5;
    int wm = warp >> 2, wn = warp & 3;

    for (int r = tid; r < BM; r += 256) {
        int m = mg0 + r, rg;
        if (gather)       rg = (m < rows) ? g_slot_token[rbeg + m] : 0;
        else if (grouped) rg = (m < rows) ? (rbeg + m) : rbeg;
        else              rg = (m < rows) ? m : 0;
        rowg[r] = rg;
    }
    __syncthreads();

    float acc[4][2][4];
#pragma unroll
    for (int a = 0; a < 4; a++)
#pragma unroll
        for (int b = 0; b < 2; b++)
#pragma unroll
            for (int c = 0; c < 4; c++) acc[a][b][c] = 0.f;

    int bn = tid & 63, bk = (tid >> 6) * 8;
    float bst[8];
    int NC = K / KC;

    // prologue: chunk 0
    gemm_issueA(sb, 0, Ahi, Alo, rowg, K, 0, tid);
    cp_commit();
    gemm_ldgB(Bp, N, 0, n0, bn, bk, bst);
    cp_wait0();
    __syncthreads();
    gemm_stsB(sm, 0, bn, bk, bst);
    __syncthreads();

    for (int ch = 0; ch < NC; ch++) {
        int buf = ch & 1;
        if (ch + 1 < NC) {
            gemm_issueA(sb, buf ^ 1, Ahi, Alo, rowg, K, (ch + 1) * KC, tid);
            cp_commit();
            gemm_ldgB(Bp, N, (ch + 1) * KC, n0, bn, bk, bst);
        }
        gemm_compute(sb, sm, buf, wm, wn, lane, acc);
        if (ch + 1 < NC) {
            cp_wait0();
            __syncthreads();
            gemm_stsB(sm, buf ^ 1, bn, bk, bst);
            __syncthreads();
        }
    }

    // writeback: warp rows wm*64 + mf*16 + (lane>>2) + half*8  (covers all 128)
#pragma unroll
    for (int mf = 0; mf < 4; mf++) {
#pragma unroll
        for (int half = 0; half < 2; half++) {
            int m = mg0 + wm * 64 + mf * 16 + (lane >> 2) + half * 8;
            if (m < rows) {
                size_t crow = (size_t)(rbeg + m);
                float* cp = C + crow * N + n0 + wn * 16 + (lane & 3) * 2;
                const float* rp = res ? res + (size_t)m * N + n0 + wn * 16 + (lane & 3) * 2 : nullptr;
#pragma unroll
                for (int nf = 0; nf < 2; nf++) {
                    float2 v;
                    v.x = acc[mf][nf][half * 2];
                    v.y = acc[mf][nf][half * 2 + 1];
                    if (rp) { v.x += rp[nf * 8]; v.y += rp[nf * 8 + 1]; }
                    *(float2*)(cp + nf * 8) = v;
                }
            }
        }
    }
}

// ======================= small kernels =======================
__global__ __launch_bounds__(256) void rmsnorm_kernel(
    const float* __restrict__ x, const float* __restrict__ w,
    float* __restrict__ yf, bf16* __restrict__ yh, bf16* __restrict__ yl)
{
    int row = blockIdx.x;
    const float* xr = x + (size_t)row * DMODEL;
    __shared__ float red[256];
    float ss = 0.f;
    const float4* x4 = (const float4*)xr;
    for (int i = threadIdx.x; i < DMODEL / 4; i += 256) {
        float4 v = x4[i];
        ss += v.x * v.x + v.y * v.y + v.z * v.z + v.w * v.w;
    }
    red[threadIdx.x] = ss;
    __syncthreads();
    for (int s = 128; s > 0; s >>= 1) {
        if (threadIdx.x < s) red[threadIdx.x] += red[threadIdx.x + s];
        __syncthreads();
    }
    float inv = rsqrtf(red[0] / (float)DMODEL + EPSF);
    for (int i = threadIdx.x; i < DMODEL; i += 256) {
        float val = xr[i] * inv * w[i];
        if (yf) yf[(size_t)row * DMODEL + i] = val;
        bf16 h, l;
        bfsplit(val, h, l);
        yh[(size_t)row * DMODEL + i] = h;
        yl[(size_t)row * DMODEL + i] = l;
    }
}

__global__ void rope_kernel(float* __restrict__ x, const int* __restrict__ pos, int nheads)
{
    int s = blockIdx.x, h = blockIdx.y, i = threadIdx.x;
    float p = (float)pos[s];
    float inv = expf(-((float)(2 * i) / 64.f) * 13.815510557964274f);
    float ang = p * inv;
    float sn, cs;
    sincosf(ang, &sn, &cs);
    float* xp = x + ((size_t)s * nheads + h) * HDIM;
    float x1 = xp[i], x2 = xp[i + 32];
    xp[i]      = x1 * cs - x2 * sn;
    xp[i + 32] = x2 * cs + x1 * sn;
}

// ---------------- flash attention: 2-way dim split, q-tile 32 ----------------
__global__ __launch_bounds__(256, 3) void flash_kernel()
{
    int bq = gridDim.x - 1 - blockIdx.x;   // largest tiles first
    int kvh = blockIdx.y;
    int tid = threadIdx.x;
    int w = tid >> 5, l = tid & 31;
    int half = l >> 4;
    int unit = w * 16 + (l & 15);          // 0..127 = 32q x 4h
    int ql = unit & 31, sub = unit >> 5;
    int qpos = bq * 32 + ql;
    int qh = kvh * 4 + sub;
    __shared__ __align__(16) float Ks[32][64];
    __shared__ __align__(16) float Vs[32][64];
    float qreg[32], o[32];
    const float4* qp = (const float4*)(g_q + ((size_t)qpos * NHEAD + qh) * HDIM + half * 32);
#pragma unroll
    for (int d4 = 0; d4 < 8; d4++) {
        float4 v = qp[d4];
        qreg[4 * d4] = v.x * 0.125f; qreg[4 * d4 + 1] = v.y * 0.125f;
        qreg[4 * d4 + 2] = v.z * 0.125f; qreg[4 * d4 + 3] = v.w * 0.125f;
        o[4 * d4] = 0.f; o[4 * d4 + 1] = 0.f; o[4 * d4 + 2] = 0.f; o[4 * d4 + 3] = 0.f;
    }
    float m = -INFINITY, lsum = 0.f;
    int kend = bq * 32 + 32;
    int qmax_w = bq * 32 + (w & 1) * 16 + 15;
    for (int kt = 0; kt < kend; kt += 32) {
        for (int i = tid; i < 32 * 16; i += 256) {
            int j = i >> 4, d4 = (i & 15) * 4;
            *(float4*)&Ks[j][d4] = *(const float4*)(g_k + ((size_t)(kt + j) * NKV + kvh) * HDIM + d4);
            *(float4*)&Vs[j][d4] = *(const float4*)(g_v + ((size_t)(kt + j) * NKV + kvh) * HDIM + d4);
        }
        __syncthreads();
        int jw = qmax_w - kt + 1;
        if (jw > 32) jw = 32;
        for (int j = 0; j < jw; j += 4) {
            float s0 = 0.f, s1 = 0.f, s2 = 0.f, s3 = 0.f;
            int hb = half * 32;
#pragma unroll
            for (int d = 0; d < 32; d += 4) {
                float4 k0 = *(const float4*)&Ks[j][hb + d];
                float4 k1 = *(const float4*)&Ks[j + 1][hb + d];
                float4 k2 = *(const float4*)&Ks[j + 2][hb + d];
                float4 k3 = *(const float4*)&Ks[j + 3][hb + d];
                s0 += qreg[d] * k0.x + qreg[d + 1] * k0.y + qreg[d + 2] * k0.z + qreg[d + 3] * k0.w;
                s1 += qreg[d] * k1.x + qreg[d + 1] * k1.y + qreg[d + 2] * k1.z + qreg[d + 3] * k1.w;
                s2 += qreg[d] * k2.x + qreg[d + 1] * k2.y + qreg[d + 2] * k2.z + qreg[d + 3] * k2.w;
                s3 += qreg[d] * k3.x + qreg[d + 1] * k3.y + qreg[d + 2] * k3.z + qreg[d + 3] * k3.w;
            }
            s0 += __shfl_xor_sync(0xFFFFFFFFu, s0, 16);
            s1 += __shfl_xor_sync(0xFFFFFFFFu, s1, 16);
            s2 += __shfl_xor_sync(0xFFFFFFFFu, s2, 16);
            s3 += __shfl_xor_sync(0xFFFFFFFFu, s3, 16);
            if (kt + j     > qpos) s0 = -1e30f;
            if (kt + j + 1 > qpos) s1 = -1e30f;
            if (kt + j + 2 > qpos) s2 = -1e30f;
            if (kt + j + 3 > qpos) s3 = -1e30f;
            float mn = fmaxf(fmaxf(fmaxf(s0, s1), fmaxf(s2, s3)), m);
            float corr = __expf(m - mn);
            float p0 = __expf(s0 - mn), p1 = __expf(s1 - mn);
            float p2 = __expf(s2 - mn), p3 = __expf(s3 - mn);
            lsum = lsum * corr + p0 + p1 + p2 + p3;
            m = mn;
#pragma unroll
            for (int d = 0; d < 32; d += 4) {
                float4 v0 = *(const float4*)&Vs[j][hb + d];
                float4 v1 = *(const float4*)&Vs[j + 1][hb + d];
                float4 v2 = *(const float4*)&Vs[j + 2][hb + d];
                float4 v3 = *(const float4*)&Vs[j + 3][hb + d];
                o[d]     = o[d]     * corr + p0 * v0.x + p1 * v1.x + p2 * v2.x + p3 * v3.x;
                o[d + 1] = o[d + 1] * corr + p0 * v0.y + p1 * v1.y + p2 * v2.y + p3 * v3.y;
                o[d + 2] = o[d + 2] * corr + p0 * v0.z + p1 * v1.z + p2 * v2.z + p3 * v3.z;
                o[d + 3] = o[d + 3] * corr + p0 * v0.w + p1 * v1.w + p2 * v2.w + p3 * v3.w;
            }
        }
        __syncthreads();
    }
    float invl = 1.f / lsum;
    size_t base = (size_t)qpos * DMODEL + (size_t)qh * HDIM + half * 32;
#pragma unroll
    for (int d = 0; d < 32; d++) {
        float val = o[d] * invl;
        bf16 h, lo;
        bfsplit(val, h, lo);
        g_at_hi[base + d] = h;
        g_at_lo[base + d] = lo;
    }
}

__global__ __launch_bounds__(128) void router_kernel(
    const float* __restrict__ T, const float* __restrict__ Wr)
{
    int t = blockIdx.x;
    __shared__ float sred[128 * 8];
    float acc[8] = {};
    const float* tr = T + (size_t)t * DMODEL;
    for (int d = threadIdx.x; d < DMODEL; d += 128) {
        float x = tr[d];
        const float* wr = Wr + (size_t)d * NEXP;
#pragma unroll
        for (int e = 0; e < 8; e++) acc[e] += x * wr[e];
    }
#pragma unroll
    for (int e = 0; e < 8; e++) sred[threadIdx.x * 8 + e] = acc[e];
    __syncthreads();
    for (int s = 64; s > 0; s >>= 1) {
        if (threadIdx.x < s) {
#pragma unroll
            for (int e = 0; e < 8; e++)
                sred[threadIdx.x * 8 + e] += sred[(threadIdx.x + s) * 8 + e];
        }
        __syncthreads();
    }
    if (threadIdx.x == 0) {
        float best = -1e30f, second = -1e30f;
        int bi = 0, si = 0;
#pragma unroll
        for (int e = 0; e < 8; e++) {
            float v = sred[e];
            if (v > best)        { second = best; si = bi; best = v; bi = e; }
            else if (v > second) { second = v; si = e; }
        }
        float p0 = 1.f / (1.f + expf(second - best));
        g_topi[2 * t] = bi;  g_topi[2 * t + 1] = si;
        g_topw[2 * t] = p0;  g_topw[2 * t + 1] = 1.f - p0;
    }
}

__global__ __launch_bounds__(256) void assign_kernel()
{
    __shared__ int cnt[NEXP], base[NEXP + 1], cur[NEXP];
    if (threadIdx.x < NEXP) cnt[threadIdx.x] = 0;
    __syncthreads();
    for (int t = threadIdx.x; t < NTOK; t += 256) {
        atomicAdd(&cnt[g_topi[2 * t]], 1);
        atomicAdd(&cnt[g_topi[2 * t + 1]], 1);
    }
    __syncthreads();
    if (threadIdx.x == 0) {
        int s = 0;
        for (int e = 0; e < NEXP; e++) { base[e] = s; s += cnt[e]; }
        base[NEXP] = s;
    }
    __syncthreads();
    if (threadIdx.x < NEXP) cur[threadIdx.x] = base[threadIdx.x];
    if (threadIdx.x < NEXP + 1) g_off[threadIdx.x] = base[threadIdx.x];
    __syncthreads();
    for (int t = threadIdx.x; t < NTOK; t += 256) {
#pragma unroll
        for (int k = 0; k < 2; k++) {
            int e = g_topi[2 * t + k];
            int slot = atomicAdd(&cur[e], 1);
            g_slot_token[slot] = t;
            g_slot_of[2 * t + k] = slot;
        }
    }
}

__global__ __launch_bounds__(512) void silu_kernel()
{
    size_t i = ((size_t)blockIdx.x * 512 + threadIdx.x) * 4;
    float4 g = *(const float4*)(g_gate + i);
    float4 u = *(const float4*)(g_up + i);
    float a0 = g.x / (1.f + __expf(-g.x)) * u.x;
    float a1 = g.y / (1.f + __expf(-g.y)) * u.y;
    float a2 = g.z / (1.f + __expf(-g.z)) * u.z;
    float a3 = g.w / (1.f + __expf(-g.w)) * u.w;
    bf16 h0, l0, h1, l1, h2, l2, h3, l3;
    bfsplit(a0, h0, l0); bfsplit(a1, h1, l1);
    bfsplit(a2, h2, l2); bfsplit(a3, h3, l3);
    bf16* ph = g_act_hi + i;
    bf16* pl = g_act_lo + i;
    ph[0] = h0; ph[1] = h1; ph[2] = h2; ph[3] = h3;
    pl[0] = l0; pl[1] = l1; pl[2] = l2; pl[3] = l3;
}

__global__ __launch_bounds__(256) void combine_kernel(
    const float* __restrict__ h2, float* __restrict__ out)
{
    int t = blockIdx.x;
    int s0 = g_slot_of[2 * t], s1 = g_slot_of[2 * t + 1];
    float w0 = g_topw[2 * t], w1 = g_topw[2 * t + 1];
    const float* d0 = g_down + (size_t)s0 * DMODEL;
    const float* d1 = g_down + (size_t)s1 * DMODEL;
    const float* hr = h2 + (size_t)t * DMODEL;
    float* orow = out + (size_t)t * DMODEL;
    for (int d = threadIdx.x; d < DMODEL; d += 256)
        orow[d] = hr[d] + w0 * d0[d] + w1 * d1[d];
}

// ======================= launch =======================
extern "C" void kernel_launch(void* const* d_in, const int* in_sizes, int n_in,
                              void* d_out, int out_size)
{
    const float* hs   = (const float*)d_in[0];
    const int*   pos  = (const int*)d_in[1];
    const float* ln1w = (const float*)d_in[2];
    const float* Wq   = (const float*)d_in[3];
    const float* Wk   = (const float*)d_in[4];
    const float* Wv   = (const float*)d_in[5];
    const float* Wo   = (const float*)d_in[6];
    const float* ln2w = (const float*)d_in[7];
    const float* Wr   = (const float*)d_in[8];
    const float* W1   = (const float*)d_in[9];
    const float* W3   = (const float*)d_in[10];
    const float* W2   = (const float*)d_in[11];
    float* out = (float*)d_out;

    cudaFuncSetAttribute(tc_gemm, cudaFuncAttributeMaxDynamicSharedMemorySize, GEMM_SMEM);

    void* p;
    cudaGetSymbolAddress(&p, g_hn_hi);  bf16* hn_hi = (bf16*)p;
    cudaGetSymbolAddress(&p, g_hn_lo);  bf16* hn_lo = (bf16*)p;
    cudaGetSymbolAddress(&p, g_q);      float* q    = (float*)p;
    cudaGetSymbolAddress(&p, g_k);      float* k    = (float*)p;
    cudaGetSymbolAddress(&p, g_v);      float* v    = (float*)p;
    cudaGetSymbolAddress(&p, g_at_hi);  bf16* at_hi = (bf16*)p;
    cudaGetSymbolAddress(&p, g_at_lo);  bf16* at_lo = (bf16*)p;
    cudaGetSymbolAddress(&p, g_h2);     float* h2   = (float*)p;
    cudaGetSymbolAddress(&p, g_tn);     float* tn   = (float*)p;
    cudaGetSymbolAddress(&p, g_tn_hi);  bf16* tn_hi = (bf16*)p;
    cudaGetSymbolAddress(&p, g_tn_lo);  bf16* tn_lo = (bf16*)p;
    cudaGetSymbolAddress(&p, g_gate);   float* gate = (float*)p;
    cudaGetSymbolAddress(&p, g_up);     float* up   = (float*)p;
    cudaGetSymbolAddress(&p, g_act_hi); bf16* ac_hi = (bf16*)p;
    cudaGetSymbolAddress(&p, g_act_lo); bf16* ac_lo = (bf16*)p;
    cudaGetSymbolAddress(&p, g_down);   float* down = (float*)p;

    // 1. rmsnorm1 -> bf16 hi/lo
    rmsnorm_kernel<<<NTOK, 256>>>(hs, ln1w, nullptr, hn_hi, hn_lo);
    // 2. QKV projections
    tc_gemm<<<dim3(32, 16, 1), 256, GEMM_SMEM>>>(hn_hi, hn_lo, Wq, q, nullptr, NTOK, 2048, DMODEL, 0, 0);
    tc_gemm<<<dim3(8, 16, 1), 256, GEMM_SMEM>>>(hn_hi, hn_lo, Wk, k, nullptr, NTOK, 512, DMODEL, 0, 0);
    tc_gemm<<<dim3(8, 16, 1), 256, GEMM_SMEM>>>(hn_hi, hn_lo, Wv, v, nullptr, NTOK, 512, DMODEL, 0, 0);
    // 3. RoPE
    rope_kernel<<<dim3(SEQ, NHEAD), 32>>>(q, pos, NHEAD);
    rope_kernel<<<dim3(SEQ, NKV), 32>>>(k, pos, NKV);
    // 4. flash attention -> attn hi/lo
    flash_kernel<<<dim3(SEQ / 32, NKV), 256>>>();
    // 5. O projection + residual
    tc_gemm<<<dim3(32, 16, 1), 256, GEMM_SMEM>>>(at_hi, at_lo, Wo, h2, hs, NTOK, 2048, DMODEL, 0, 0);
    // 6. rmsnorm2
    rmsnorm_kernel<<<NTOK, 256>>>(h2, ln2w, tn, tn_hi, tn_lo);
    // 7-8. router + assignment
    router_kernel<<<NTOK, 128>>>(tn, Wr);
    assign_kernel<<<1, 256>>>();
    // 9. gate & up grouped GEMMs (gather)
    tc_gemm<<<dim3(112, 16, 8), 256, GEMM_SMEM>>>(tn_hi, tn_lo, W1, gate, nullptr, 0, FDIM, DMODEL, 1, 1);
    tc_gemm<<<dim3(112, 16, 8), 256, GEMM_SMEM>>>(tn_hi, tn_lo, W3, up, nullptr, 0, FDIM, DMODEL, 1, 1);
    // 10. silu(gate)*up -> act hi/lo
    silu_kernel<<<(int)((size_t)NSLOT * FDIM / 4 / 512), 512>>>();
    // 11. down grouped GEMM (slot-space A)
    tc_gemm<<<dim3(32, 16, 8), 256, GEMM_SMEM>>>(ac_hi, ac_lo, W2, down, nullptr, 0, DMODEL, FDIM, 1, 0);
    // 12. combine with residual
    combine_kernel<<<NTOK, 256>>>(h2, out);
}